// round 3
// baseline (speedup 1.0000x reference)
#include <cuda_runtime.h>
#include <math.h>

#define Bsz 4096
#define Ssz 16
#define Gsz 128
#define Esz 256
#define Hsz 512
#define Psz 16
#define KCAT (Esz + Hsz)   /* 768 */
#define NG   (4 * Hsz)     /* 2048 */

// ---------------- scratch (device globals; no allocation allowed) ----------------
__device__ float g_emb[Bsz * Ssz * Esz];    // (B,S,E)
__device__ float g_ref[Bsz * Ssz * Hsz];    // encoder hidden states (B,S,H)
__device__ float g_u2 [Bsz * Ssz * Hsz];    // Wref2 @ ref + bref2
__device__ float g_inpenc[Bsz * Ssz * NG];  // emb @ enc_Wih^T (gate-interleaved)
__device__ float g_inpdec[Bsz * Ssz * NG];  // emb @ dec_Wih^T (gate-interleaved)
__device__ float g_dec0g[NG];               // dec_input0 @ dec_Wih^T
__device__ float g_h0 [Bsz * Hsz];
__device__ float g_h1 [Bsz * Hsz];
__device__ float g_c  [Bsz * Hsz];
__device__ float g_qp [Bsz * Hsz];
__device__ float g_mask[Bsz * Ssz];
__device__ float g_ll [Bsz];
__device__ int   g_pi [Bsz * Psz];
__device__ int   g_sel[Bsz];
__device__ float g_Wenc[NG * KCAT];         // gate-interleaved [Wih|Whh]
__device__ float g_benc[NG];
__device__ float g_Wdec[NG * KCAT];
__device__ float g_bdec[NG];

static __device__ __forceinline__ float sigf(float x) { return 1.0f / (1.0f + expf(-x)); }

// ---- packed f32x2 helpers (FFMA2 path: 2 FMA/lane/issue on sm_103a) ----
static __device__ __forceinline__ void ffma2(unsigned long long& d,
                                             unsigned long long a,
                                             unsigned long long b)
{
    asm("fma.rn.f32x2 %0, %1, %2, %0;" : "+l"(d) : "l"(a), "l"(b));
}
static __device__ __forceinline__ float2 unp2(unsigned long long v)
{
    float2 r;
    asm("mov.b64 {%0, %1}, %2;" : "=f"(r.x), "=f"(r.y) : "l"(v));
    return r;
}

// ---------------- weight reorder: new row 4*j+g <- old row g*H+j, cols = [Wih|Whh] ----
__global__ void reorder_k(const float* __restrict__ Wih, const float* __restrict__ Whh,
                          const float* __restrict__ b,
                          float* __restrict__ Wcat, float* __restrict__ bcat)
{
    int idx = blockIdx.x * blockDim.x + threadIdx.x;
    if (idx >= NG * KCAT) return;
    int r = idx / KCAT, k = idx % KCAT;
    int j = r >> 2, g = r & 3;
    int ro = g * Hsz + j;
    Wcat[idx] = (k < Esz) ? Wih[ro * Esz + k] : Whh[ro * Hsz + (k - Esz)];
    if (k == 0) bcat[r] = b[ro];
}

// ---------------- dec_input0 gate projection: warp per output ----------------
__global__ void dec0_k(const float* __restrict__ dec0, const float* __restrict__ Wdec,
                       float* __restrict__ out)
{
    int n = blockIdx.x * 8 + (threadIdx.x >> 5);
    int lane = threadIdx.x & 31;
    const float* wr = Wdec + (size_t)n * KCAT;
    float s = 0.f;
#pragma unroll
    for (int k = lane; k < Esz; k += 32) s += dec0[k] * wr[k];
#pragma unroll
    for (int o = 16; o; o >>= 1) s += __shfl_xor_sync(0xffffffffu, s, o);
    if (lane == 0) out[n] = s;
}

// ---------------- init state ----------------
__global__ void init_k()
{
    int i = blockIdx.x * blockDim.x + threadIdx.x;
    if (i < Bsz * Hsz) { g_h0[i] = 0.f; g_c[i] = 0.f; }
    if (i < Bsz * Ssz) g_mask[i] = 0.f;
    if (i < Bsz)       g_ll[i] = 0.f;
}

// ---------------- SGEMM: C[m,n] = sum_k A[m,k]*W[n,k] (+bias) ; MODE1 = fused LSTM ----
// A is stored DUPLICATED in smem ({a,a} pairs) so the inner loop is pure LDS + FFMA2.
#define BM 128
#define BN 128
#define BK 8
#define BMP (2 * BM + 8)   /* 264 floats per k-row, duplicated A */
#define BNP 136

template <int MODE>
__global__ __launch_bounds__(256, 2) void gemm_k(
    const float* __restrict__ A, int lda,
    const float* __restrict__ W, int ldw, int K,
    const float* __restrict__ bias,
    float* __restrict__ C, int N,
    const float* __restrict__ inp, long long mstride,
    const int* __restrict__ sel, int trow,
    float* __restrict__ cstate, float* __restrict__ hout,
    float* __restrict__ refout)
{
    __shared__ __align__(16) float As[2][BK][BMP];
    __shared__ __align__(16) float Bs[2][BK][BNP];

    const int tid = threadIdx.x;
    const int tx = tid & 15, ty = tid >> 4;
    const int bm = blockIdx.y * BM, bn = blockIdx.x * BN;

    const int l_m = tid >> 1, l_k = (tid & 1) * 4;

    const float* ap = A + (size_t)(bm + l_m) * lda + l_k;
    const float* wp = W + (size_t)(bn + l_m) * ldw + l_k;

    unsigned long long acc2[8][4];
#pragma unroll
    for (int i = 0; i < 8; i++)
#pragma unroll
        for (int j = 0; j < 4; j++) acc2[i][j] = 0ULL;

    const int nk = K / BK;

    float4 av = *reinterpret_cast<const float4*>(ap);
    float4 wv = *reinterpret_cast<const float4*>(wp);

    int buf = 0;
    {
        float2* d0 = reinterpret_cast<float2*>(&As[0][l_k + 0][2 * l_m]);
        float2* d1 = reinterpret_cast<float2*>(&As[0][l_k + 1][2 * l_m]);
        float2* d2 = reinterpret_cast<float2*>(&As[0][l_k + 2][2 * l_m]);
        float2* d3 = reinterpret_cast<float2*>(&As[0][l_k + 3][2 * l_m]);
        *d0 = make_float2(av.x, av.x);
        *d1 = make_float2(av.y, av.y);
        *d2 = make_float2(av.z, av.z);
        *d3 = make_float2(av.w, av.w);
    }
    Bs[0][l_k + 0][l_m] = wv.x; Bs[0][l_k + 1][l_m] = wv.y;
    Bs[0][l_k + 2][l_m] = wv.z; Bs[0][l_k + 3][l_m] = wv.w;
    __syncthreads();

    for (int kt = 0; kt < nk; kt++) {
        float4 av2, wv2;
        if (kt + 1 < nk) {
            av2 = *reinterpret_cast<const float4*>(ap + (kt + 1) * BK);
            wv2 = *reinterpret_cast<const float4*>(wp + (kt + 1) * BK);
        }
#pragma unroll
        for (int kk = 0; kk < BK; kk++) {
            unsigned long long aa[8];
            *reinterpret_cast<ulonglong2*>(&aa[0]) = *reinterpret_cast<const ulonglong2*>(&As[buf][kk][ty * 16]);
            *reinterpret_cast<ulonglong2*>(&aa[2]) = *reinterpret_cast<const ulonglong2*>(&As[buf][kk][ty * 16 + 4]);
            *reinterpret_cast<ulonglong2*>(&aa[4]) = *reinterpret_cast<const ulonglong2*>(&As[buf][kk][ty * 16 + 8]);
            *reinterpret_cast<ulonglong2*>(&aa[6]) = *reinterpret_cast<const ulonglong2*>(&As[buf][kk][ty * 16 + 12]);
            unsigned long long bp[4];
            *reinterpret_cast<ulonglong2*>(&bp[0]) = *reinterpret_cast<const ulonglong2*>(&Bs[buf][kk][tx * 8]);
            *reinterpret_cast<ulonglong2*>(&bp[2]) = *reinterpret_cast<const ulonglong2*>(&Bs[buf][kk][tx * 8 + 4]);
#pragma unroll
            for (int i = 0; i < 8; i++)
#pragma unroll
                for (int j = 0; j < 4; j++) ffma2(acc2[i][j], aa[i], bp[j]);
        }
        if (kt + 1 < nk) {
            buf ^= 1;
            float2* d0 = reinterpret_cast<float2*>(&As[buf][l_k + 0][2 * l_m]);
            float2* d1 = reinterpret_cast<float2*>(&As[buf][l_k + 1][2 * l_m]);
            float2* d2 = reinterpret_cast<float2*>(&As[buf][l_k + 2][2 * l_m]);
            float2* d3 = reinterpret_cast<float2*>(&As[buf][l_k + 3][2 * l_m]);
            *d0 = make_float2(av2.x, av2.x);
            *d1 = make_float2(av2.y, av2.y);
            *d2 = make_float2(av2.z, av2.z);
            *d3 = make_float2(av2.w, av2.w);
            Bs[buf][l_k + 0][l_m] = wv2.x; Bs[buf][l_k + 1][l_m] = wv2.y;
            Bs[buf][l_k + 2][l_m] = wv2.z; Bs[buf][l_k + 3][l_m] = wv2.w;
            __syncthreads();
        }
    }

    const int n0 = bn + tx * 8;
    if (MODE == 0) {
        float bb[8];
#pragma unroll
        for (int j = 0; j < 8; j++) bb[j] = bias ? bias[n0 + j] : 0.f;
#pragma unroll
        for (int i = 0; i < 8; i++) {
            int m = bm + ty * 8 + i;
            float o[8];
#pragma unroll
            for (int j = 0; j < 4; j++) {
                float2 v = unp2(acc2[i][j]);
                o[2 * j]     = v.x + bb[2 * j];
                o[2 * j + 1] = v.y + bb[2 * j + 1];
            }
            float* cp = C + (size_t)m * N + n0;
            *reinterpret_cast<float4*>(cp)     = make_float4(o[0], o[1], o[2], o[3]);
            *reinterpret_cast<float4*>(cp + 4) = make_float4(o[4], o[5], o[6], o[7]);
        }
    } else {
        // LSTM epilogue: columns are gate-interleaved, 4 per unit (i,f,g,o)
        float bb[8];
#pragma unroll
        for (int j = 0; j < 8; j++) bb[j] = bias[n0 + j];
        const int unit0 = n0 >> 2;  // 2 units per thread
#pragma unroll
        for (int i = 0; i < 8; i++) {
            int m = bm + ty * 8 + i;
            long long off = (long long)m * mstride + (long long)(sel ? sel[m] : trow) * NG;
            const float* ip = inp + off + n0;
            float4 g0 = *reinterpret_cast<const float4*>(ip);
            float4 g1 = *reinterpret_cast<const float4*>(ip + 4);
            float g[8] = {g0.x, g0.y, g0.z, g0.w, g1.x, g1.y, g1.z, g1.w};
#pragma unroll
            for (int j = 0; j < 4; j++) {
                float2 v = unp2(acc2[i][j]);
                g[2 * j]     += v.x + bb[2 * j];
                g[2 * j + 1] += v.y + bb[2 * j + 1];
            }
#pragma unroll
            for (int u = 0; u < 2; u++) {
                int unit = unit0 + u;
                float ig = sigf(g[4 * u + 0]);
                float fg = sigf(g[4 * u + 1]);
                float gg = tanhf(g[4 * u + 2]);
                float og = sigf(g[4 * u + 3]);
                size_t ci = (size_t)m * Hsz + unit;
                float cn = fg * cstate[ci] + ig * gg;
                float hn = og * tanhf(cn);
                cstate[ci] = cn;
                hout[ci]   = hn;
                if (refout) refout[((size_t)m * Ssz + trow) * Hsz + unit] = hn;
            }
        }
    }
}

// ---------------- pointer step: logits -> log_softmax -> argmax -> sel/mask/ll ----------
__global__ void pointer_k(const float* __restrict__ qp, const float* __restrict__ u2,
                          const float* __restrict__ Vec2,
                          float* __restrict__ mask, float* __restrict__ ll,
                          int* __restrict__ pi, int* __restrict__ sel, int p)
{
    const int b = blockIdx.x;
    const int tid = threadIdx.x;
    const int lane = tid & 31, w = tid >> 5;
    __shared__ float qs[Hsz], vs[Hsz], ls[Ssz];

    qs[tid]       = qp[(size_t)b * Hsz + tid];
    qs[tid + 256] = qp[(size_t)b * Hsz + 256 + tid];
    vs[tid]       = Vec2[tid];
    vs[tid + 256] = Vec2[tid + 256];
    __syncthreads();

#pragma unroll
    for (int q = 0; q < 2; q++) {
        int ss = 2 * w + q;
        const float* up = u2 + ((size_t)b * Ssz + ss) * Hsz;
        float acc = 0.f;
#pragma unroll
        for (int it = 0; it < Hsz / 32; it++) {
            int h = lane + 32 * it;
            acc += vs[h] * tanhf(qs[h] + up[h]);
        }
#pragma unroll
        for (int o = 16; o; o >>= 1) acc += __shfl_xor_sync(0xffffffffu, acc, o);
        if (lane == 0) ls[ss] = 10.0f * acc - 1e8f * mask[b * Ssz + ss];
    }
    __syncthreads();

    if (w == 0) {
        float v  = (lane < Ssz) ? ls[lane] : -INFINITY;
        int   id = (lane < Ssz) ? lane : Ssz;
        float bv = v; int bi = id;
#pragma unroll
        for (int o = 8; o; o >>= 1) {
            float ov = __shfl_xor_sync(0xffffffffu, bv, o);
            int   oi = __shfl_xor_sync(0xffffffffu, bi, o);
            if (ov > bv || (ov == bv && oi < bi)) { bv = ov; bi = oi; }
        }
        float ex = (lane < Ssz) ? expf(v - bv) : 0.f;
#pragma unroll
        for (int o = 16; o; o >>= 1) ex += __shfl_xor_sync(0xffffffffu, ex, o);
        if (lane == 0) {
            float lse = bv + logf(ex);
            ll[b] += bv - lse;            // chosen log_p == max - lse
            pi[b * Psz + p] = bi;
            sel[b] = bi;
            mask[b * Ssz + bi] += 1.0f;
        }
    }
}

// ---------------- final mapping + output pack ----------------
__global__ void out_k(const int* __restrict__ pi, const float* __restrict__ ll,
                      void* __restrict__ out, int out_size)
{
    int b = blockIdx.x * blockDim.x + threadIdx.x;
    if (b >= Bsz) return;
    const int nodes[Psz] = {0,0,0,0, 1,1,1,1, 2,2,2,2, 3,3,3,3};
    int mp[Psz];
#pragma unroll
    for (int k = 0; k < Psz; k++) mp[k] = -1;
#pragma unroll
    for (int q = 0; q < Psz; q++) mp[pi[b * Psz + q]] = nodes[q];

    if (out_size >= Bsz * Psz + Bsz) {
        float* o = (float*)out;
#pragma unroll
        for (int k = 0; k < Psz; k++) o[b * Psz + k] = (float)mp[k];
        o[Bsz * Psz + b] = ll[b];
    } else {
        int* o = (int*)out;
#pragma unroll
        for (int k = 0; k < Psz; k++) o[b * Psz + k] = mp[k];
    }
}

// ---------------- host side ----------------
extern "C" void kernel_launch(void* const* d_in, const int* in_sizes, int n_in,
                              void* d_out, int out_size)
{
    const float* x        = (const float*)d_in[0];
    const float* emb_W    = (const float*)d_in[1];
    const float* enc_Wih  = (const float*)d_in[2];
    const float* enc_Whh  = (const float*)d_in[3];
    const float* enc_b    = (const float*)d_in[4];
    const float* dec_Wih  = (const float*)d_in[5];
    const float* dec_Whh  = (const float*)d_in[6];
    const float* dec_b    = (const float*)d_in[7];
    const float* Wq2      = (const float*)d_in[8];
    const float* bq2      = (const float*)d_in[9];
    const float* Wref2    = (const float*)d_in[10];
    const float* bref2    = (const float*)d_in[11];
    const float* Vec2     = (const float*)d_in[12];
    const float* dec0     = (const float*)d_in[13];

    float *emb, *ref, *u2, *inpenc, *inpdec, *dec0g, *h0, *h1, *c, *qp, *mask, *ll;
    float *Wenc, *benc, *Wdec, *bdec;
    int *pi, *sel;
    cudaGetSymbolAddress((void**)&emb,    g_emb);
    cudaGetSymbolAddress((void**)&ref,    g_ref);
    cudaGetSymbolAddress((void**)&u2,     g_u2);
    cudaGetSymbolAddress((void**)&inpenc, g_inpenc);
    cudaGetSymbolAddress((void**)&inpdec, g_inpdec);
    cudaGetSymbolAddress((void**)&dec0g,  g_dec0g);
    cudaGetSymbolAddress((void**)&h0,     g_h0);
    cudaGetSymbolAddress((void**)&h1,     g_h1);
    cudaGetSymbolAddress((void**)&c,      g_c);
    cudaGetSymbolAddress((void**)&qp,     g_qp);
    cudaGetSymbolAddress((void**)&mask,   g_mask);
    cudaGetSymbolAddress((void**)&ll,     g_ll);
    cudaGetSymbolAddress((void**)&pi,     g_pi);
    cudaGetSymbolAddress((void**)&sel,    g_sel);
    cudaGetSymbolAddress((void**)&Wenc,   g_Wenc);
    cudaGetSymbolAddress((void**)&benc,   g_benc);
    cudaGetSymbolAddress((void**)&Wdec,   g_Wdec);
    cudaGetSymbolAddress((void**)&bdec,   g_bdec);

    const int RT = NG * KCAT;
    reorder_k<<<(RT + 255) / 256, 256>>>(enc_Wih, enc_Whh, enc_b, Wenc, benc);
    reorder_k<<<(RT + 255) / 256, 256>>>(dec_Wih, dec_Whh, dec_b, Wdec, bdec);
    init_k<<<(Bsz * Hsz + 255) / 256, 256>>>();
    dec0_k<<<NG / 8, 256>>>(dec0, Wdec, dec0g);

    // emb = x @ emb_W^T   (M=B*S, N=E, K=G)
    gemm_k<0><<<dim3(Esz / BN, (Bsz * Ssz) / BM), 256>>>(
        x, Gsz, emb_W, Gsz, Gsz, nullptr,
        emb, Esz, nullptr, 0, nullptr, 0, nullptr, nullptr, nullptr);

    // inp_enc = emb @ enc_Wih^T (gate-interleaved) : one big parallel GEMM
    gemm_k<0><<<dim3(NG / BN, (Bsz * Ssz) / BM), 256>>>(
        emb, Esz, Wenc, KCAT, Esz, nullptr,
        inpenc, NG, nullptr, 0, nullptr, 0, nullptr, nullptr, nullptr);

    // inp_dec = emb @ dec_Wih^T
    gemm_k<0><<<dim3(NG / BN, (Bsz * Ssz) / BM), 256>>>(
        emb, Esz, Wdec, KCAT, Esz, nullptr,
        inpdec, NG, nullptr, 0, nullptr, 0, nullptr, nullptr, nullptr);

    // ---- encoder: per-step GEMM only over h (K=512), input gates precomputed ----
    float* hc = h0;
    float* hn = h1;
    for (int t = 0; t < Ssz; t++) {
        gemm_k<1><<<dim3(NG / BN, Bsz / BM), 256>>>(
            hc, Hsz, Wenc + Esz, KCAT, Hsz, benc,
            nullptr, 0, inpenc, (long long)Ssz * NG, nullptr, t, c, hn, ref);
        float* tmp = hc; hc = hn; hn = tmp;
    }

    // u2 = ref @ Wref2^T + bref2   (M=B*S, N=H, K=H)
    gemm_k<0><<<dim3(Hsz / BN, (Bsz * Ssz) / BM), 256>>>(
        ref, Hsz, Wref2, Hsz, Hsz, bref2,
        u2, Hsz, nullptr, 0, nullptr, 0, nullptr, nullptr, nullptr);

    // ---- decoder ----
    for (int p = 0; p < Psz; p++) {
        if (p == 0) {
            gemm_k<1><<<dim3(NG / BN, Bsz / BM), 256>>>(
                hc, Hsz, Wdec + Esz, KCAT, Hsz, bdec,
                nullptr, 0, dec0g, 0LL, nullptr, 0, c, hn, nullptr);
        } else {
            gemm_k<1><<<dim3(NG / BN, Bsz / BM), 256>>>(
                hc, Hsz, Wdec + Esz, KCAT, Hsz, bdec,
                nullptr, 0, inpdec, (long long)Ssz * NG, sel, 0, c, hn, nullptr);
        }
        float* tmp = hc; hc = hn; hn = tmp;

        // qp = h @ Wq2^T + bq2
        gemm_k<0><<<dim3(Hsz / BN, Bsz / BM), 256>>>(
            hc, Hsz, Wq2, Hsz, Hsz, bq2,
            qp, Hsz, nullptr, 0, nullptr, 0, nullptr, nullptr, nullptr);

        pointer_k<<<Bsz, 256>>>(qp, u2, Vec2, mask, ll, pi, sel, p);
    }

    out_k<<<(Bsz + 255) / 256, 256>>>(pi, ll, d_out, out_size);
}

// round 5
// speedup vs baseline: 1.1496x; 1.1496x over previous
#include <cuda_runtime.h>
#include <cuda_bf16.h>
#include <math.h>
#include <stdint.h>

#define Bsz 4096
#define Ssz 16
#define Gsz 128
#define Esz 256
#define Hsz 512
#define Psz 16
#define KCAT (Esz + Hsz)   /* 768 */
#define NG   (4 * Hsz)     /* 2048 */
#define MROWS (Bsz * Ssz)  /* 65536 */

typedef __nv_bfloat16 bf16;
typedef __nv_bfloat162 bf162;

// ---------------- scratch (device globals; no allocation allowed) ----------------
__device__ float g_u2 [MROWS * Hsz];
__device__ float g_inpenc[MROWS * NG];
__device__ float g_inpdec[MROWS * NG];
__device__ float g_dec0g[NG];
__device__ float g_c  [Bsz * Hsz];
__device__ float g_qp [Bsz * Hsz];
__device__ float g_mask[Bsz * Ssz];
__device__ float g_ll [Bsz];
__device__ int   g_pi [Bsz * Psz];
__device__ int   g_sel[Bsz];
__device__ float g_Wenc[NG * KCAT];
__device__ float g_benc[NG];
__device__ float g_Wdec[NG * KCAT];
__device__ float g_bdec[NG];

// bf16 3-way split operands
__device__ __align__(128) bf16 g_X0[MROWS * Gsz],  g_X1[MROWS * Gsz],  g_X2[MROWS * Gsz];
__device__ __align__(128) bf16 g_E0[MROWS * Esz],  g_E1[MROWS * Esz],  g_E2[MROWS * Esz];
__device__ __align__(128) bf16 g_R0[MROWS * Hsz],  g_R1[MROWS * Hsz],  g_R2[MROWS * Hsz];
__device__ __align__(128) bf16 g_Ha0[Bsz * Hsz], g_Ha1[Bsz * Hsz], g_Ha2[Bsz * Hsz];
__device__ __align__(128) bf16 g_Hb0[Bsz * Hsz], g_Hb1[Bsz * Hsz], g_Hb2[Bsz * Hsz];
__device__ __align__(128) bf16 g_EW0[Esz * Gsz],  g_EW1[Esz * Gsz],  g_EW2[Esz * Gsz];
__device__ __align__(128) bf16 g_WE0[NG * Esz],   g_WE1[NG * Esz],   g_WE2[NG * Esz];
__device__ __align__(128) bf16 g_WD0[NG * Esz],   g_WD1[NG * Esz],   g_WD2[NG * Esz];
__device__ __align__(128) bf16 g_WEH0[NG * Hsz],  g_WEH1[NG * Hsz],  g_WEH2[NG * Hsz];
__device__ __align__(128) bf16 g_WDH0[NG * Hsz],  g_WDH1[NG * Hsz],  g_WDH2[NG * Hsz];
__device__ __align__(128) bf16 g_WQ0[Hsz * Hsz],  g_WQ1[Hsz * Hsz],  g_WQ2s[Hsz * Hsz];
__device__ __align__(128) bf16 g_WR0[Hsz * Hsz],  g_WR1[Hsz * Hsz],  g_WR2[Hsz * Hsz];

static __device__ __forceinline__ float sigf(float x) { return 1.0f / (1.0f + expf(-x)); }

// ---------------- low-level helpers ----------------
static __device__ __forceinline__ uint32_t smem_u32(const void* p) {
    uint32_t a;
    asm("{ .reg .u64 t; cvta.to.shared.u64 t, %1; cvt.u32.u64 %0, t; }" : "=r"(a) : "l"(p));
    return a;
}
static __device__ __forceinline__ void ldsm4(uint32_t* r, uint32_t addr) {
    asm volatile("ldmatrix.sync.aligned.m8n8.x4.shared.b16 {%0,%1,%2,%3}, [%4];"
        : "=r"(r[0]), "=r"(r[1]), "=r"(r[2]), "=r"(r[3]) : "r"(addr));
}
static __device__ __forceinline__ void mma16816(float* d, const uint32_t* a, uint32_t b0, uint32_t b1) {
    asm volatile("mma.sync.aligned.m16n8k16.row.col.f32.bf16.bf16.f32 "
        "{%0,%1,%2,%3}, {%4,%5,%6,%7}, {%8,%9}, {%0,%1,%2,%3};"
        : "+f"(d[0]), "+f"(d[1]), "+f"(d[2]), "+f"(d[3])
        : "r"(a[0]), "r"(a[1]), "r"(a[2]), "r"(a[3]), "r"(b0), "r"(b1));
}
#define CPA(s, g) asm volatile("cp.async.cg.shared.global [%0], [%1], 16;" :: "r"(s), "l"(g))
#define CPC()     asm volatile("cp.async.commit_group;" ::: "memory")
template <int Ngrp> static __device__ __forceinline__ void cpwait() {
    asm volatile("cp.async.wait_group %0;" :: "n"(Ngrp) : "memory");
}

static __device__ __forceinline__ void split1(float v, bf16& b0, bf16& b1, bf16& b2) {
    b0 = __float2bfloat16(v);
    float r = v - __bfloat162float(b0);
    b1 = __float2bfloat16(r);
    r -= __bfloat162float(b1);
    b2 = __float2bfloat16(r);
}

// ---------------- 3-way bf16 split of an fp32 matrix ----------------
__global__ void split3_k(const float* __restrict__ src, int lds, int K,
                         bf16* __restrict__ d0, bf16* __restrict__ d1,
                         bf16* __restrict__ d2, int total)
{
    int idx = blockIdx.x * blockDim.x + threadIdx.x;
    if (idx >= total) return;
    int r = idx / K, k = idx - r * K;
    float v = src[(size_t)r * lds + k];
    bf16 b0, b1, b2;
    split1(v, b0, b1, b2);
    d0[idx] = b0; d1[idx] = b1; d2[idx] = b2;
}

// ---------------- weight reorder: new row 4*j+g <- old row g*H+j, cols = [Wih|Whh] ----
__global__ void reorder_k(const float* __restrict__ Wih, const float* __restrict__ Whh,
                          const float* __restrict__ b,
                          float* __restrict__ Wcat, float* __restrict__ bcat)
{
    int idx = blockIdx.x * blockDim.x + threadIdx.x;
    if (idx >= NG * KCAT) return;
    int r = idx / KCAT, k = idx % KCAT;
    int j = r >> 2, g = r & 3;
    int ro = g * Hsz + j;
    Wcat[idx] = (k < Esz) ? Wih[ro * Esz + k] : Whh[ro * Hsz + (k - Esz)];
    if (k == 0) bcat[r] = b[ro];
}

// ---------------- dec_input0 gate projection ----------------
__global__ void dec0_k(const float* __restrict__ dec0, const float* __restrict__ Wdec,
                       float* __restrict__ out)
{
    int n = blockIdx.x * 8 + (threadIdx.x >> 5);
    int lane = threadIdx.x & 31;
    const float* wr = Wdec + (size_t)n * KCAT;
    float s = 0.f;
#pragma unroll
    for (int k = lane; k < Esz; k += 32) s += dec0[k] * wr[k];
#pragma unroll
    for (int o = 16; o; o >>= 1) s += __shfl_xor_sync(0xffffffffu, s, o);
    if (lane == 0) out[n] = s;
}

// ---------------- init state ----------------
__global__ void init_k()
{
    int i = blockIdx.x * blockDim.x + threadIdx.x;
    if (i < Bsz * Hsz) {
        g_c[i] = 0.f;
        g_Ha0[i] = __float2bfloat16(0.f);
        g_Ha1[i] = __float2bfloat16(0.f);
        g_Ha2[i] = __float2bfloat16(0.f);
    }
    if (i < Bsz * Ssz) g_mask[i] = 0.f;
    if (i < Bsz)       g_ll[i] = 0.f;
}

// ================= HMMA 3-split bf16 GEMM =================
// C[m,n] = sum_k A[m,k]*W[n,k], 6-term split: a0b0+a1b0+a2b0+a0b1+a1b1+a0b2
// Tile 128x128xK, BK=32, 8 warps (4m x 2n), warp tile 32x64, cp.async double buffer.
// MODE 0: fp32 out (+bias). MODE 1: bf16-split out. MODE 2: fused LSTM epilogue.
#define RS 80                 /* smem row stride bytes (40 bf16) — conflict-free ldmatrix */
#define OPB (128 * RS)        /* 10240 bytes per operand tile */
#define STGB (6 * OPB)        /* 61440 per stage */
#define HSM (2 * STGB)        /* 122880 total dynamic smem */

template <int MODE>
__global__ void __launch_bounds__(256, 1) hmma_k(
    const bf16* __restrict__ A0, const bf16* __restrict__ A1, const bf16* __restrict__ A2,
    const bf16* __restrict__ B0, const bf16* __restrict__ B1, const bf16* __restrict__ B2,
    int K, const float* __restrict__ bias,
    float* __restrict__ C, int N,
    bf16* __restrict__ S0, bf16* __restrict__ S1, bf16* __restrict__ S2,
    const float* __restrict__ inp, long long mstride, const int* __restrict__ sel, int trow,
    float* __restrict__ cstate,
    bf16* __restrict__ H0, bf16* __restrict__ H1, bf16* __restrict__ H2,
    bf16* __restrict__ R0, bf16* __restrict__ R1, bf16* __restrict__ R2)
{
    extern __shared__ __align__(128) char smem[];
    const uint32_t sb = smem_u32(smem);
    const int tid = threadIdx.x, wid = tid >> 5, lane = tid & 31;
    const int wm = wid & 3, wn = wid >> 2;
    const int bn = blockIdx.x * 128, bm = blockIdx.y * 128;

    float D[2][8][4];
#pragma unroll
    for (int i = 0; i < 2; i++)
#pragma unroll
        for (int j = 0; j < 8; j++)
#pragma unroll
            for (int q = 0; q < 4; q++) D[i][j][q] = 0.f;

    // global load indexing: thread covers 2x16B of each operand tile per stage
    const int grow = tid >> 1;                 // 0..127
    const int gco  = (tid & 1) * 16;           // element offset 0 / 16
    const bf16* gA[3] = {A0 + (size_t)(bm + grow) * K, A1 + (size_t)(bm + grow) * K, A2 + (size_t)(bm + grow) * K};
    const bf16* gB[3] = {B0 + (size_t)(bn + grow) * K, B1 + (size_t)(bn + grow) * K, B2 + (size_t)(bn + grow) * K};
    const uint32_t srow = sb + grow * RS + (tid & 1) * 32;

    auto stage_load = [&](int cc, int buf) {
        const int kc = cc * 32 + gco;
        const uint32_t s0 = srow + buf * STGB;
#pragma unroll
        for (int s = 0; s < 3; s++) {
            CPA(s0 + s * OPB, gA[s] + kc);
            CPA(s0 + s * OPB + 16, gA[s] + kc + 8);
            CPA(s0 + (3 + s) * OPB, gB[s] + kc);
            CPA(s0 + (3 + s) * OPB + 16, gB[s] + kc + 8);
        }
    };

    // ldmatrix lane addressing
    const int la = lane & 7, lb3 = (lane >> 3) & 1, lb4 = (lane >> 4) & 1;
    const uint32_t aAddr = sb + (uint32_t)(wm * 32 + la + lb3 * 8) * RS + (uint32_t)(lb4 * 8) * 2;
    const uint32_t bAddr = sb + 3 * OPB + (uint32_t)(wn * 64 + la + lb4 * 8) * RS + (uint32_t)(lb3 * 8) * 2;

    const int chunks = K >> 5;
    stage_load(0, 0); CPC();

    for (int cc = 0; cc < chunks; cc++) {
        const int buf = cc & 1;
        if (cc + 1 < chunks) { stage_load(cc + 1, buf ^ 1); CPC(); cpwait<1>(); }
        else cpwait<0>();
        __syncthreads();

#pragma unroll
        for (int ks = 0; ks < 2; ks++) {
            uint32_t a[3][2][4];
#pragma unroll
            for (int s = 0; s < 3; s++) {
                ldsm4(a[s][0], aAddr + buf * STGB + s * OPB + ks * 32);
                ldsm4(a[s][1], aAddr + buf * STGB + s * OPB + ks * 32 + 16 * RS);
            }
            // bs = 0: as in {0,1,2}; bs = 1: as in {0,1}; bs = 2: as in {0}
#pragma unroll
            for (int bs = 0; bs < 3; bs++) {
                uint32_t b[4][4];
#pragma unroll
                for (int n16 = 0; n16 < 4; n16++)
                    ldsm4(b[n16], bAddr + buf * STGB + bs * OPB + ks * 32 + n16 * 16 * RS);
                const int nas = (bs == 0) ? 3 : (bs == 1 ? 2 : 1);
#pragma unroll
                for (int as = 0; as < 3; as++) {
                    if (as >= nas) break;
#pragma unroll
                    for (int mi = 0; mi < 2; mi++)
#pragma unroll
                        for (int n16 = 0; n16 < 4; n16++) {
                            mma16816(D[mi][2 * n16],     a[as][mi], b[n16][0], b[n16][1]);
                            mma16816(D[mi][2 * n16 + 1], a[as][mi], b[n16][2], b[n16][3]);
                        }
                }
            }
        }
        __syncthreads();
    }

    // ---------------- epilogues ----------------
    const int c4 = lane & 3, r4 = lane >> 2;
    if (MODE == 0 || MODE == 1) {
#pragma unroll
        for (int mi = 0; mi < 2; mi++) {
            const int m0 = bm + wm * 32 + mi * 16 + r4;
#pragma unroll
            for (int nt = 0; nt < 8; nt++) {
                const int n0 = bn + wn * 64 + nt * 8 + c4 * 2;
                float bx = 0.f, by = 0.f;
                if (MODE == 0 && bias) { float2 bb = *(const float2*)(bias + n0); bx = bb.x; by = bb.y; }
                float v0 = D[mi][nt][0] + bx, v1 = D[mi][nt][1] + by;
                float v2 = D[mi][nt][2] + bx, v3 = D[mi][nt][3] + by;
                size_t o0 = (size_t)m0 * N + n0;
                size_t o1 = o0 + (size_t)8 * N;
                if (MODE == 0) {
                    *(float2*)(C + o0) = make_float2(v0, v1);
                    *(float2*)(C + o1) = make_float2(v2, v3);
                } else {
                    bf16 x0, x1, x2, y0, y1, y2;
                    split1(v0, x0, x1, x2); split1(v1, y0, y1, y2);
                    bf162 p;
                    p.x = x0; p.y = y0; *(bf162*)(S0 + o0) = p;
                    p.x = x1; p.y = y1; *(bf162*)(S1 + o0) = p;
                    p.x = x2; p.y = y2; *(bf162*)(S2 + o0) = p;
                    split1(v2, x0, x1, x2); split1(v3, y0, y1, y2);
                    p.x = x0; p.y = y0; *(bf162*)(S0 + o1) = p;
                    p.x = x1; p.y = y1; *(bf162*)(S1 + o1) = p;
                    p.x = x2; p.y = y2; *(bf162*)(S2 + o1) = p;
                }
            }
        }
    } else {
        // LSTM: cols are gate-interleaved (i,f,g,o per unit). Lane pair (c4, c4^1)
        // holds (i,f) / (g,o); exchange via shfl, even-c4 lanes compute one unit.
#pragma unroll
        for (int mi = 0; mi < 2; mi++) {
            const int mA = bm + wm * 32 + mi * 16 + r4;
            const int mB = mA + 8;
            const long long offA = (long long)mA * mstride + (long long)(sel ? sel[mA] : trow) * NG;
            const long long offB = (long long)mB * mstride + (long long)(sel ? sel[mB] : trow) * NG;
#pragma unroll
            for (int nt = 0; nt < 8; nt++) {
                float d0 = D[mi][nt][0], d1 = D[mi][nt][1];
                float d2 = D[mi][nt][2], d3 = D[mi][nt][3];
                float e0 = __shfl_xor_sync(0xffffffffu, d0, 1);
                float e1 = __shfl_xor_sync(0xffffffffu, d1, 1);
                float e2 = __shfl_xor_sync(0xffffffffu, d2, 1);
                float e3 = __shfl_xor_sync(0xffffffffu, d3, 1);
                if (!(c4 & 1)) {
                    const int ucol = bn + wn * 64 + nt * 8 + c4 * 2;  // 4-aligned
                    const int unit = ucol >> 2;
                    const float4 bb = *(const float4*)(bias + ucol);
                    const float4 gA = *(const float4*)(inp + offA + ucol);
                    const float4 gB = *(const float4*)(inp + offB + ucol);
                    {
                        float gi = sigf(d0 + gA.x + bb.x);
                        float gf = sigf(d1 + gA.y + bb.y);
                        float gg = tanhf(e0 + gA.z + bb.z);
                        float go = sigf(e1 + gA.w + bb.w);
                        size_t ci = (size_t)mA * Hsz + unit;
                        float cn = gf * cstate[ci] + gi * gg;
                        float hn = go * tanhf(cn);
                        cstate[ci] = cn;
                        bf16 h0, h1, h2; split1(hn, h0, h1, h2);
                        H0[ci] = h0; H1[ci] = h1; H2[ci] = h2;
                        if (R0) {
                            size_t ri = ((size_t)mA * Ssz + trow) * Hsz + unit;
                            R0[ri] = h0; R1[ri] = h1; R2[ri] = h2;
                        }
                    }
                    {
                        float gi = sigf(d2 + gB.x + bb.x);
                        float gf = sigf(d3 + gB.y + bb.y);
                        float gg = tanhf(e2 + gB.z + bb.z);
                        float go = sigf(e3 + gB.w + bb.w);
                        size_t ci = (size_t)mB * Hsz + unit;
                        float cn = gf * cstate[ci] + gi * gg;
                        float hn = go * tanhf(cn);
                        cstate[ci] = cn;
                        bf16 h0, h1, h2; split1(hn, h0, h1, h2);
                        H0[ci] = h0; H1[ci] = h1; H2[ci] = h2;
                        if (R0) {
                            size_t ri = ((size_t)mB * Ssz + trow) * Hsz + unit;
                            R0[ri] = h0; R1[ri] = h1; R2[ri] = h2;
                        }
                    }
                }
            }
        }
    }
}

// ---------------- pointer step ----------------
__global__ void pointer_k(const float* __restrict__ qp, const float* __restrict__ u2,
                          const float* __restrict__ Vec2,
                          float* __restrict__ mask, float* __restrict__ ll,
                          int* __restrict__ pi, int* __restrict__ sel, int p)
{
    const int b = blockIdx.x;
    const int tid = threadIdx.x;
    const int lane = tid & 31, w = tid >> 5;
    __shared__ float qs[Hsz], vs[Hsz], ls[Ssz];

    qs[tid]       = qp[(size_t)b * Hsz + tid];
    qs[tid + 256] = qp[(size_t)b * Hsz + 256 + tid];
    vs[tid]       = Vec2[tid];
    vs[tid + 256] = Vec2[tid + 256];
    __syncthreads();

#pragma unroll
    for (int q = 0; q < 2; q++) {
        int ss = 2 * w + q;
        const float* up = u2 + ((size_t)b * Ssz + ss) * Hsz;
        float acc = 0.f;
#pragma unroll
        for (int it = 0; it < Hsz / 32; it++) {
            int h = lane + 32 * it;
            acc += vs[h] * tanhf(qs[h] + up[h]);
        }
#pragma unroll
        for (int o = 16; o; o >>= 1) acc += __shfl_xor_sync(0xffffffffu, acc, o);
        if (lane == 0) ls[ss] = 10.0f * acc - 1e8f * mask[b * Ssz + ss];
    }
    __syncthreads();

    if (w == 0) {
        float v  = (lane < Ssz) ? ls[lane] : -INFINITY;
        int   id = (lane < Ssz) ? lane : Ssz;
        float bv = v; int bi = id;
#pragma unroll
        for (int o = 8; o; o >>= 1) {
            float ov = __shfl_xor_sync(0xffffffffu, bv, o);
            int   oi = __shfl_xor_sync(0xffffffffu, bi, o);
            if (ov > bv || (ov == bv && oi < bi)) { bv = ov; bi = oi; }
        }
        float ex = (lane < Ssz) ? expf(v - bv) : 0.f;
#pragma unroll
        for (int o = 16; o; o >>= 1) ex += __shfl_xor_sync(0xffffffffu, ex, o);
        if (lane == 0) {
            float lse = bv + logf(ex);
            ll[b] += bv - lse;
            pi[b * Psz + p] = bi;
            sel[b] = bi;
            mask[b * Ssz + bi] += 1.0f;
        }
    }
}

// ---------------- final mapping + output pack ----------------
__global__ void out_k(const int* __restrict__ pi, const float* __restrict__ ll,
                      void* __restrict__ out, int out_size)
{
    int b = blockIdx.x * blockDim.x + threadIdx.x;
    if (b >= Bsz) return;
    const int nodes[Psz] = {0,0,0,0, 1,1,1,1, 2,2,2,2, 3,3,3,3};
    int mp[Psz];
#pragma unroll
    for (int k = 0; k < Psz; k++) mp[k] = -1;
#pragma unroll
    for (int q = 0; q < Psz; q++) mp[pi[b * Psz + q]] = nodes[q];

    if (out_size >= Bsz * Psz + Bsz) {
        float* o = (float*)out;
#pragma unroll
        for (int k = 0; k < Psz; k++) o[b * Psz + k] = (float)mp[k];
        o[Bsz * Psz + b] = ll[b];
    } else {
        int* o = (int*)out;
#pragma unroll
        for (int k = 0; k < Psz; k++) o[b * Psz + k] = mp[k];
    }
}

// ---------------- host side ----------------
extern "C" void kernel_launch(void* const* d_in, const int* in_sizes, int n_in,
                              void* d_out, int out_size)
{
    const float* x        = (const float*)d_in[0];
    const float* emb_W    = (const float*)d_in[1];
    const float* enc_Wih  = (const float*)d_in[2];
    const float* enc_Whh  = (const float*)d_in[3];
    const float* enc_b    = (const float*)d_in[4];
    const float* dec_Wih  = (const float*)d_in[5];
    const float* dec_Whh  = (const float*)d_in[6];
    const float* dec_b    = (const float*)d_in[7];
    const float* Wq2      = (const float*)d_in[8];
    const float* bq2      = (const float*)d_in[9];
    const float* Wref2    = (const float*)d_in[10];
    const float* bref2    = (const float*)d_in[11];
    const float* Vec2     = (const float*)d_in[12];
    const float* dec0     = (const float*)d_in[13];

    float *u2, *inpenc, *inpdec, *dec0g, *c, *qp, *mask, *ll;
    float *Wenc, *benc, *Wdec, *bdec;
    int *pi, *sel;
    bf16 *X0,*X1,*X2, *E0,*E1,*E2, *R0,*R1,*R2;
    bf16 *Ha0,*Ha1,*Ha2, *Hb0,*Hb1,*Hb2;
    bf16 *EW0,*EW1,*EW2, *WE0,*WE1,*WE2, *WD0,*WD1,*WD2;
    bf16 *WEH0,*WEH1,*WEH2, *WDH0,*WDH1,*WDH2, *WQ0,*WQ1,*WQ2p, *WR0,*WR1,*WR2;

    cudaGetSymbolAddress((void**)&u2,     g_u2);
    cudaGetSymbolAddress((void**)&inpenc, g_inpenc);
    cudaGetSymbolAddress((void**)&inpdec, g_inpdec);
    cudaGetSymbolAddress((void**)&dec0g,  g_dec0g);
    cudaGetSymbolAddress((void**)&c,      g_c);
    cudaGetSymbolAddress((void**)&qp,     g_qp);
    cudaGetSymbolAddress((void**)&mask,   g_mask);
    cudaGetSymbolAddress((void**)&ll,     g_ll);
    cudaGetSymbolAddress((void**)&pi,     g_pi);
    cudaGetSymbolAddress((void**)&sel,    g_sel);
    cudaGetSymbolAddress((void**)&Wenc,   g_Wenc);
    cudaGetSymbolAddress((void**)&benc,   g_benc);
    cudaGetSymbolAddress((void**)&Wdec,   g_Wdec);
    cudaGetSymbolAddress((void**)&bdec,   g_bdec);
    cudaGetSymbolAddress((void**)&X0, g_X0); cudaGetSymbolAddress((void**)&X1, g_X1); cudaGetSymbolAddress((void**)&X2, g_X2);
    cudaGetSymbolAddress((void**)&E0, g_E0); cudaGetSymbolAddress((void**)&E1, g_E1); cudaGetSymbolAddress((void**)&E2, g_E2);
    cudaGetSymbolAddress((void**)&R0, g_R0); cudaGetSymbolAddress((void**)&R1, g_R1); cudaGetSymbolAddress((void**)&R2, g_R2);
    cudaGetSymbolAddress((void**)&Ha0, g_Ha0); cudaGetSymbolAddress((void**)&Ha1, g_Ha1); cudaGetSymbolAddress((void**)&Ha2, g_Ha2);
    cudaGetSymbolAddress((void**)&Hb0, g_Hb0); cudaGetSymbolAddress((void**)&Hb1, g_Hb1); cudaGetSymbolAddress((void**)&Hb2, g_Hb2);
    cudaGetSymbolAddress((void**)&EW0, g_EW0); cudaGetSymbolAddress((void**)&EW1, g_EW1); cudaGetSymbolAddress((void**)&EW2, g_EW2);
    cudaGetSymbolAddress((void**)&WE0, g_WE0); cudaGetSymbolAddress((void**)&WE1, g_WE1); cudaGetSymbolAddress((void**)&WE2, g_WE2);
    cudaGetSymbolAddress((void**)&WD0, g_WD0); cudaGetSymbolAddress((void**)&WD1, g_WD1); cudaGetSymbolAddress((void**)&WD2, g_WD2);
    cudaGetSymbolAddress((void**)&WEH0, g_WEH0); cudaGetSymbolAddress((void**)&WEH1, g_WEH1); cudaGetSymbolAddress((void**)&WEH2, g_WEH2);
    cudaGetSymbolAddress((void**)&WDH0, g_WDH0); cudaGetSymbolAddress((void**)&WDH1, g_WDH1); cudaGetSymbolAddress((void**)&WDH2, g_WDH2);
    cudaGetSymbolAddress((void**)&WQ0, g_WQ0); cudaGetSymbolAddress((void**)&WQ1, g_WQ1); cudaGetSymbolAddress((void**)&WQ2p, g_WQ2s);
    cudaGetSymbolAddress((void**)&WR0, g_WR0); cudaGetSymbolAddress((void**)&WR1, g_WR1); cudaGetSymbolAddress((void**)&WR2, g_WR2);

    cudaFuncSetAttribute(hmma_k<0>, cudaFuncAttributeMaxDynamicSharedMemorySize, HSM);
    cudaFuncSetAttribute(hmma_k<1>, cudaFuncAttributeMaxDynamicSharedMemorySize, HSM);
    cudaFuncSetAttribute(hmma_k<2>, cudaFuncAttributeMaxDynamicSharedMemorySize, HSM);

    const int RT = NG * KCAT;
    reorder_k<<<(RT + 255) / 256, 256>>>(enc_Wih, enc_Whh, enc_b, Wenc, benc);
    reorder_k<<<(RT + 255) / 256, 256>>>(dec_Wih, dec_Whh, dec_b, Wdec, bdec);
    init_k<<<(Bsz * Hsz + 255) / 256, 256>>>();
    dec0_k<<<NG / 8, 256>>>(dec0, Wdec, dec0g);

    // operand splits
    split3_k<<<(MROWS * Gsz + 255) / 256, 256>>>(x, Gsz, Gsz, X0, X1, X2, MROWS * Gsz);
    split3_k<<<(Esz * Gsz + 255) / 256, 256>>>(emb_W, Gsz, Gsz, EW0, EW1, EW2, Esz * Gsz);
    split3_k<<<(NG * Esz + 255) / 256, 256>>>(Wenc, KCAT, Esz, WE0, WE1, WE2, NG * Esz);
    split3_k<<<(NG * Esz + 255) / 256, 256>>>(Wdec, KCAT, Esz, WD0, WD1, WD2, NG * Esz);
    split3_k<<<(NG * Hsz + 255) / 256, 256>>>(Wenc + Esz, KCAT, Hsz, WEH0, WEH1, WEH2, NG * Hsz);
    split3_k<<<(NG * Hsz + 255) / 256, 256>>>(Wdec + Esz, KCAT, Hsz, WDH0, WDH1, WDH2, NG * Hsz);
    split3_k<<<(Hsz * Hsz + 255) / 256, 256>>>(Wq2, Hsz, Hsz, WQ0, WQ1, WQ2p, Hsz * Hsz);
    split3_k<<<(Hsz * Hsz + 255) / 256, 256>>>(Wref2, Hsz, Hsz, WR0, WR1, WR2, Hsz * Hsz);

    // emb = x @ emb_W^T -> bf16 splits E
    hmma_k<1><<<dim3(Esz / 128, MROWS / 128), 256, HSM>>>(
        X0, X1, X2, EW0, EW1, EW2, Gsz, nullptr, nullptr, Esz,
        E0, E1, E2, nullptr, 0, nullptr, 0, nullptr,
        nullptr, nullptr, nullptr, nullptr, nullptr, nullptr);

    // inp_enc / inp_dec tables (fp32)
    hmma_k<0><<<dim3(NG / 128, MROWS / 128), 256, HSM>>>(
        E0, E1, E2, WE0, WE1, WE2, Esz, nullptr, inpenc, NG,
        nullptr, nullptr, nullptr, nullptr, 0, nullptr, 0, nullptr,
        nullptr, nullptr, nullptr, nullptr, nullptr, nullptr);
    hmma_k<0><<<dim3(NG / 128, MROWS / 128), 256, HSM>>>(
        E0, E1, E2, WD0, WD1, WD2, Esz, nullptr, inpdec, NG,
        nullptr, nullptr, nullptr, nullptr, 0, nullptr, 0, nullptr,
        nullptr, nullptr, nullptr, nullptr, nullptr, nullptr);

    // ---- encoder: 16 fused LSTM steps ----
    bf16 *hc0 = Ha0, *hc1 = Ha1, *hc2 = Ha2;
    bf16 *hn0 = Hb0, *hn1 = Hb1, *hn2 = Hb2;
    for (int t = 0; t < Ssz; t++) {
        hmma_k<2><<<dim3(NG / 128, Bsz / 128), 256, HSM>>>(
            hc0, hc1, hc2, WEH0, WEH1, WEH2, Hsz, benc, nullptr, NG,
            nullptr, nullptr, nullptr,
            inpenc, (long long)Ssz * NG, nullptr, t,
            c, hn0, hn1, hn2, R0, R1, R2);
        bf16* t0 = hc0; hc0 = hn0; hn0 = t0;
        bf16* t1 = hc1; hc1 = hn1; hn1 = t1;
        bf16* t2 = hc2; hc2 = hn2; hn2 = t2;
    }

    // u2 = ref @ Wref2^T + bref2
    hmma_k<0><<<dim3(Hsz / 128, MROWS / 128), 256, HSM>>>(
        R0, R1, R2, WR0, WR1, WR2, Hsz, bref2, u2, Hsz,
        nullptr, nullptr, nullptr, nullptr, 0, nullptr, 0, nullptr,
        nullptr, nullptr, nullptr, nullptr, nullptr, nullptr);

    // ---- decoder: 16 fused steps + pointer ----
    for (int p = 0; p < Psz; p++) {
        if (p == 0) {
            hmma_k<2><<<dim3(NG / 128, Bsz / 128), 256, HSM>>>(
                hc0, hc1, hc2, WDH0, WDH1, WDH2, Hsz, bdec, nullptr, NG,
                nullptr, nullptr, nullptr,
                dec0g, 0LL, nullptr, 0,
                c, hn0, hn1, hn2, nullptr, nullptr, nullptr);
        } else {
            hmma_k<2><<<dim3(NG / 128, Bsz / 128), 256, HSM>>>(
                hc0, hc1, hc2, WDH0, WDH1, WDH2, Hsz, bdec, nullptr, NG,
                nullptr, nullptr, nullptr,
                inpdec, (long long)Ssz * NG, sel, 0,
                c, hn0, hn1, hn2, nullptr, nullptr, nullptr);
        }
        bf16* t0 = hc0; hc0 = hn0; hn0 = t0;
        bf16* t1 = hc1; hc1 = hn1; hn1 = t1;
        bf16* t2 = hc2; hc2 = hn2; hn2 = t2;

        // qp = h @ Wq2^T + bq2
        hmma_k<0><<<dim3(Hsz / 128, Bsz / 128), 256, HSM>>>(
            hc0, hc1, hc2, WQ0, WQ1, WQ2p, Hsz, bq2, qp, Hsz,
            nullptr, nullptr, nullptr, nullptr, 0, nullptr, 0, nullptr,
            nullptr, nullptr, nullptr, nullptr, nullptr, nullptr);

        pointer_k<<<Bsz, 256>>>(qp, u2, Vec2, mask, ll, pi, sel, p);
    }

    out_k<<<(Bsz + 255) / 256, 256>>>(pi, ll, d_out, out_size);
}

// round 6
// speedup vs baseline: 2.0839x; 1.8127x over previous
#include <cuda_runtime.h>
#include <cuda_fp16.h>
#include <math.h>
#include <stdint.h>

#define Bsz 4096
#define Ssz 16
#define Gsz 128
#define Esz 256
#define Hsz 512
#define Psz 16
#define KCAT (Esz + Hsz)   /* 768 */
#define NG   (4 * Hsz)     /* 2048 */
#define MROWS (Bsz * Ssz)  /* 65536 */

#define SCALE_UP 64.0f
#define SC (1.0f / 4096.0f)   /* 2^-12 epilogue unscale */

// ---------------- scratch (device globals; no allocation allowed) ----------------
__device__ float g_u2 [MROWS * Hsz];
__device__ float g_inpenc[MROWS * NG];
__device__ float g_inpdec[MROWS * NG];
__device__ float g_dec0g[NG];
__device__ float g_c  [Bsz * Hsz];
__device__ float g_qp [Bsz * Hsz];
__device__ float g_mask[Bsz * Ssz];
__device__ float g_ll [Bsz];
__device__ int   g_pi [Bsz * Psz];
__device__ int   g_sel[Bsz];
__device__ float g_Wenc[NG * KCAT];
__device__ float g_benc[NG];
__device__ float g_Wdec[NG * KCAT];
__device__ float g_bdec[NG];

// fp16 2-way split operands (all pre-scaled by 64)
__device__ __align__(128) __half g_X0[MROWS * Gsz],  g_X1[MROWS * Gsz];
__device__ __align__(128) __half g_E0[MROWS * Esz],  g_E1[MROWS * Esz];
__device__ __align__(128) __half g_R0[MROWS * Hsz],  g_R1[MROWS * Hsz];
__device__ __align__(128) __half g_Ha0[Bsz * Hsz], g_Ha1[Bsz * Hsz];
__device__ __align__(128) __half g_Hb0[Bsz * Hsz], g_Hb1[Bsz * Hsz];
__device__ __align__(128) __half g_EW0[Esz * Gsz],  g_EW1[Esz * Gsz];
__device__ __align__(128) __half g_WE0[NG * Esz],   g_WE1[NG * Esz];
__device__ __align__(128) __half g_WD0[NG * Esz],   g_WD1[NG * Esz];
__device__ __align__(128) __half g_WEH0[NG * Hsz],  g_WEH1[NG * Hsz];
__device__ __align__(128) __half g_WDH0[NG * Hsz],  g_WDH1[NG * Hsz];
__device__ __align__(128) __half g_WQ0[Hsz * Hsz],  g_WQ1[Hsz * Hsz];
__device__ __align__(128) __half g_WR0[Hsz * Hsz],  g_WR1[Hsz * Hsz];

static __device__ __forceinline__ float sigf(float x) { return 1.0f / (1.0f + expf(-x)); }

// ---------------- low-level helpers ----------------
static __device__ __forceinline__ uint32_t smem_u32(const void* p) {
    uint32_t a;
    asm("{ .reg .u64 t; cvta.to.shared.u64 t, %1; cvt.u32.u64 %0, t; }" : "=r"(a) : "l"(p));
    return a;
}
static __device__ __forceinline__ void ldsm4(uint32_t* r, uint32_t addr) {
    asm volatile("ldmatrix.sync.aligned.m8n8.x4.shared.b16 {%0,%1,%2,%3}, [%4];"
        : "=r"(r[0]), "=r"(r[1]), "=r"(r[2]), "=r"(r[3]) : "r"(addr));
}
static __device__ __forceinline__ void mma16816(float* d, const uint32_t* a, uint32_t b0, uint32_t b1) {
    asm volatile("mma.sync.aligned.m16n8k16.row.col.f32.f16.f16.f32 "
        "{%0,%1,%2,%3}, {%4,%5,%6,%7}, {%8,%9}, {%0,%1,%2,%3};"
        : "+f"(d[0]), "+f"(d[1]), "+f"(d[2]), "+f"(d[3])
        : "r"(a[0]), "r"(a[1]), "r"(a[2]), "r"(a[3]), "r"(b0), "r"(b1));
}
#define CPA(s, g) asm volatile("cp.async.cg.shared.global [%0], [%1], 16;" :: "r"(s), "l"(g))
#define CPC()     asm volatile("cp.async.commit_group;" ::: "memory")
template <int Ngrp> static __device__ __forceinline__ void cpwait() {
    asm volatile("cp.async.wait_group %0;" :: "n"(Ngrp) : "memory");
}

// scaled fp16 2-split: v -> (h0, h1) with h0 + h1 == 64*v (to fp16x2 precision)
static __device__ __forceinline__ void split1h(float v, __half& h0, __half& h1) {
    float vs = v * SCALE_UP;
    h0 = __float2half_rn(vs);
    h1 = __float2half_rn(vs - __half2float(h0));
}

// ---------------- scaled fp16 split of an fp32 matrix ----------------
__global__ void split2_k(const float* __restrict__ src, int lds, int K,
                         __half* __restrict__ d0, __half* __restrict__ d1, int total)
{
    int idx = blockIdx.x * blockDim.x + threadIdx.x;
    if (idx >= total) return;
    int r = idx / K, k = idx - r * K;
    float v = src[(size_t)r * lds + k];
    __half h0, h1;
    split1h(v, h0, h1);
    d0[idx] = h0; d1[idx] = h1;
}

// ---------------- weight reorder: new row 4*j+g <- old row g*H+j, cols = [Wih|Whh] ----
__global__ void reorder_k(const float* __restrict__ Wih, const float* __restrict__ Whh,
                          const float* __restrict__ b,
                          float* __restrict__ Wcat, float* __restrict__ bcat)
{
    int idx = blockIdx.x * blockDim.x + threadIdx.x;
    if (idx >= NG * KCAT) return;
    int r = idx / KCAT, k = idx % KCAT;
    int j = r >> 2, g = r & 3;
    int ro = g * Hsz + j;
    Wcat[idx] = (k < Esz) ? Wih[ro * Esz + k] : Whh[ro * Hsz + (k - Esz)];
    if (k == 0) bcat[r] = b[ro];
}

// ---------------- dec_input0 gate projection ----------------
__global__ void dec0_k(const float* __restrict__ dec0, const float* __restrict__ Wdec,
                       float* __restrict__ out)
{
    int n = blockIdx.x * 8 + (threadIdx.x >> 5);
    int lane = threadIdx.x & 31;
    const float* wr = Wdec + (size_t)n * KCAT;
    float s = 0.f;
#pragma unroll
    for (int k = lane; k < Esz; k += 32) s += dec0[k] * wr[k];
#pragma unroll
    for (int o = 16; o; o >>= 1) s += __shfl_xor_sync(0xffffffffu, s, o);
    if (lane == 0) out[n] = s;
}

// ---------------- init state ----------------
__global__ void init_k()
{
    int i = blockIdx.x * blockDim.x + threadIdx.x;
    if (i < Bsz * Hsz) {
        g_c[i] = 0.f;
        g_Ha0[i] = __float2half(0.f);
        g_Ha1[i] = __float2half(0.f);
    }
    if (i < Bsz * Ssz) g_mask[i] = 0.f;
    if (i < Bsz)       g_ll[i] = 0.f;
}

// ================= HMMA fp16 2-split GEMM =================
// C[m,n] = SC * sum_k As[m,k]*Ws[n,k], 3 terms: a0b0 + a1b0 + a0b1
// Tile 128x128xK, BK=32, 8 warps (4m x 2n), warp tile 32x64, cp.async double buffer.
// MODE 0: fp32 out (+bias). MODE 1: fp16-split out. MODE 2: fused LSTM epilogue.
#define RS 80                 /* smem row stride bytes — conflict-free ldmatrix */
#define OPB (128 * RS)        /* 10240 bytes per operand tile */
#define STGB (4 * OPB)        /* 40960 per stage */
#define HSM (2 * STGB)        /* 81920 total dynamic smem */

template <int MODE>
__global__ void __launch_bounds__(256, 2) hmma_k(
    const __half* __restrict__ A0, const __half* __restrict__ A1,
    const __half* __restrict__ B0, const __half* __restrict__ B1,
    int K, const float* __restrict__ bias,
    float* __restrict__ C, int N,
    __half* __restrict__ S0, __half* __restrict__ S1,
    const float* __restrict__ inp, long long mstride, const int* __restrict__ sel, int trow,
    float* __restrict__ cstate,
    __half* __restrict__ H0, __half* __restrict__ H1,
    __half* __restrict__ R0, __half* __restrict__ R1)
{
    extern __shared__ __align__(128) char smem[];
    const uint32_t sb = smem_u32(smem);
    const int tid = threadIdx.x, wid = tid >> 5, lane = tid & 31;
    const int wm = wid & 3, wn = wid >> 2;
    const int bn = blockIdx.x * 128, bm = blockIdx.y * 128;

    float D[2][8][4];
#pragma unroll
    for (int i = 0; i < 2; i++)
#pragma unroll
        for (int j = 0; j < 8; j++)
#pragma unroll
            for (int q = 0; q < 4; q++) D[i][j][q] = 0.f;

    const int grow = tid >> 1;
    const int gco  = (tid & 1) * 16;
    const __half* gA[2] = {A0 + (size_t)(bm + grow) * K, A1 + (size_t)(bm + grow) * K};
    const __half* gB[2] = {B0 + (size_t)(bn + grow) * K, B1 + (size_t)(bn + grow) * K};
    const uint32_t srow = sb + grow * RS + (tid & 1) * 32;

    auto stage_load = [&](int cc, int buf) {
        const int kc = cc * 32 + gco;
        const uint32_t s0 = srow + buf * STGB;
#pragma unroll
        for (int s = 0; s < 2; s++) {
            CPA(s0 + s * OPB, gA[s] + kc);
            CPA(s0 + s * OPB + 16, gA[s] + kc + 8);
            CPA(s0 + (2 + s) * OPB, gB[s] + kc);
            CPA(s0 + (2 + s) * OPB + 16, gB[s] + kc + 8);
        }
    };

    const int la = lane & 7, lb3 = (lane >> 3) & 1, lb4 = (lane >> 4) & 1;
    const uint32_t aAddr = sb + (uint32_t)(wm * 32 + la + lb3 * 8) * RS + (uint32_t)(lb4 * 8) * 2;
    const uint32_t bAddr = sb + 2 * OPB + (uint32_t)(wn * 64 + la + lb4 * 8) * RS + (uint32_t)(lb3 * 8) * 2;

    const int chunks = K >> 5;
    stage_load(0, 0); CPC();

    for (int cc = 0; cc < chunks; cc++) {
        const int buf = cc & 1;
        if (cc + 1 < chunks) { stage_load(cc + 1, buf ^ 1); CPC(); cpwait<1>(); }
        else cpwait<0>();
        __syncthreads();

#pragma unroll
        for (int ks = 0; ks < 2; ks++) {
            uint32_t a[2][2][4];
#pragma unroll
            for (int s = 0; s < 2; s++) {
                ldsm4(a[s][0], aAddr + buf * STGB + s * OPB + ks * 32);
                ldsm4(a[s][1], aAddr + buf * STGB + s * OPB + ks * 32 + 16 * RS);
            }
            // bs = 0: as in {0,1}; bs = 1: as in {0}
#pragma unroll
            for (int bs = 0; bs < 2; bs++) {
                uint32_t b[4][4];
#pragma unroll
                for (int n16 = 0; n16 < 4; n16++)
                    ldsm4(b[n16], bAddr + buf * STGB + bs * OPB + ks * 32 + n16 * 16 * RS);
                const int nas = (bs == 0) ? 2 : 1;
#pragma unroll
                for (int as = 0; as < 2; as++) {
                    if (as >= nas) break;
#pragma unroll
                    for (int mi = 0; mi < 2; mi++)
#pragma unroll
                        for (int n16 = 0; n16 < 4; n16++) {
                            mma16816(D[mi][2 * n16],     a[as][mi], b[n16][0], b[n16][1]);
                            mma16816(D[mi][2 * n16 + 1], a[as][mi], b[n16][2], b[n16][3]);
                        }
                }
            }
        }
        __syncthreads();
    }

    // ---------------- epilogues ----------------
    const int c4 = lane & 3, r4 = lane >> 2;
    if (MODE == 0 || MODE == 1) {
#pragma unroll
        for (int mi = 0; mi < 2; mi++) {
            const int m0 = bm + wm * 32 + mi * 16 + r4;
#pragma unroll
            for (int nt = 0; nt < 8; nt++) {
                const int n0 = bn + wn * 64 + nt * 8 + c4 * 2;
                float bx = 0.f, by = 0.f;
                if (MODE == 0 && bias) { float2 bb = *(const float2*)(bias + n0); bx = bb.x; by = bb.y; }
                float v0 = D[mi][nt][0] * SC + bx, v1 = D[mi][nt][1] * SC + by;
                float v2 = D[mi][nt][2] * SC + bx, v3 = D[mi][nt][3] * SC + by;
                size_t o0 = (size_t)m0 * N + n0;
                size_t o1 = o0 + (size_t)8 * N;
                if (MODE == 0) {
                    *(float2*)(C + o0) = make_float2(v0, v1);
                    *(float2*)(C + o1) = make_float2(v2, v3);
                } else {
                    __half x0, x1, y0, y1;
                    __half2 p;
                    split1h(v0, x0, x1); split1h(v1, y0, y1);
                    p.x = x0; p.y = y0; *(__half2*)(S0 + o0) = p;
                    p.x = x1; p.y = y1; *(__half2*)(S1 + o0) = p;
                    split1h(v2, x0, x1); split1h(v3, y0, y1);
                    p.x = x0; p.y = y0; *(__half2*)(S0 + o1) = p;
                    p.x = x1; p.y = y1; *(__half2*)(S1 + o1) = p;
                }
            }
        }
    } else {
        // LSTM: cols gate-interleaved (i,f,g,o per unit). Lane pair exchange via shfl.
#pragma unroll
        for (int mi = 0; mi < 2; mi++) {
            const int mA = bm + wm * 32 + mi * 16 + r4;
            const int mB = mA + 8;
            const long long offA = (long long)mA * mstride + (long long)(sel ? sel[mA] : trow) * NG;
            const long long offB = (long long)mB * mstride + (long long)(sel ? sel[mB] : trow) * NG;
#pragma unroll
            for (int nt = 0; nt < 8; nt++) {
                float d0 = D[mi][nt][0] * SC, d1 = D[mi][nt][1] * SC;
                float d2 = D[mi][nt][2] * SC, d3 = D[mi][nt][3] * SC;
                float e0 = __shfl_xor_sync(0xffffffffu, d0, 1);
                float e1 = __shfl_xor_sync(0xffffffffu, d1, 1);
                float e2 = __shfl_xor_sync(0xffffffffu, d2, 1);
                float e3 = __shfl_xor_sync(0xffffffffu, d3, 1);
                if (!(c4 & 1)) {
                    const int ucol = bn + wn * 64 + nt * 8 + c4 * 2;
                    const int unit = ucol >> 2;
                    const float4 bb = *(const float4*)(bias + ucol);
                    const float4 gA = *(const float4*)(inp + offA + ucol);
                    const float4 gB = *(const float4*)(inp + offB + ucol);
                    {
                        float gi = sigf(d0 + gA.x + bb.x);
                        float gf = sigf(d1 + gA.y + bb.y);
                        float gg = tanhf(e0 + gA.z + bb.z);
                        float go = sigf(e1 + gA.w + bb.w);
                        size_t ci = (size_t)mA * Hsz + unit;
                        float cn = gf * cstate[ci] + gi * gg;
                        float hn = go * tanhf(cn);
                        cstate[ci] = cn;
                        __half h0, h1; split1h(hn, h0, h1);
                        H0[ci] = h0; H1[ci] = h1;
                        if (R0) {
                            size_t ri = ((size_t)mA * Ssz + trow) * Hsz + unit;
                            R0[ri] = h0; R1[ri] = h1;
                        }
                    }
                    {
                        float gi = sigf(d2 + gB.x + bb.x);
                        float gf = sigf(d3 + gB.y + bb.y);
                        float gg = tanhf(e2 + gB.z + bb.z);
                        float go = sigf(e3 + gB.w + bb.w);
                        size_t ci = (size_t)mB * Hsz + unit;
                        float cn = gf * cstate[ci] + gi * gg;
                        float hn = go * tanhf(cn);
                        cstate[ci] = cn;
                        __half h0, h1; split1h(hn, h0, h1);
                        H0[ci] = h0; H1[ci] = h1;
                        if (R0) {
                            size_t ri = ((size_t)mB * Ssz + trow) * Hsz + unit;
                            R0[ri] = h0; R1[ri] = h1;
                        }
                    }
                }
            }
        }
    }
}

// ---------------- pointer step ----------------
__global__ void pointer_k(const float* __restrict__ qp, const float* __restrict__ u2,
                          const float* __restrict__ Vec2,
                          float* __restrict__ mask, float* __restrict__ ll,
                          int* __restrict__ pi, int* __restrict__ sel, int p)
{
    const int b = blockIdx.x;
    const int tid = threadIdx.x;
    const int lane = tid & 31, w = tid >> 5;
    __shared__ float qs[Hsz], vs[Hsz], ls[Ssz];

    qs[tid]       = qp[(size_t)b * Hsz + tid];
    qs[tid + 256] = qp[(size_t)b * Hsz + 256 + tid];
    vs[tid]       = Vec2[tid];
    vs[tid + 256] = Vec2[tid + 256];
    __syncthreads();

#pragma unroll
    for (int q = 0; q < 2; q++) {
        int ss = 2 * w + q;
        const float* up = u2 + ((size_t)b * Ssz + ss) * Hsz;
        float acc = 0.f;
#pragma unroll
        for (int it = 0; it < Hsz / 32; it++) {
            int h = lane + 32 * it;
            acc += vs[h] * tanhf(qs[h] + up[h]);
        }
#pragma unroll
        for (int o = 16; o; o >>= 1) acc += __shfl_xor_sync(0xffffffffu, acc, o);
        if (lane == 0) ls[ss] = 10.0f * acc - 1e8f * mask[b * Ssz + ss];
    }
    __syncthreads();

    if (w == 0) {
        float v  = (lane < Ssz) ? ls[lane] : -INFINITY;
        int   id = (lane < Ssz) ? lane : Ssz;
        float bv = v; int bi = id;
#pragma unroll
        for (int o = 8; o; o >>= 1) {
            float ov = __shfl_xor_sync(0xffffffffu, bv, o);
            int   oi = __shfl_xor_sync(0xffffffffu, bi, o);
            if (ov > bv || (ov == bv && oi < bi)) { bv = ov; bi = oi; }
        }
        float ex = (lane < Ssz) ? expf(v - bv) : 0.f;
#pragma unroll
        for (int o = 16; o; o >>= 1) ex += __shfl_xor_sync(0xffffffffu, ex, o);
        if (lane == 0) {
            float lse = bv + logf(ex);
            ll[b] += bv - lse;
            pi[b * Psz + p] = bi;
            sel[b] = bi;
            mask[b * Ssz + bi] += 1.0f;
        }
    }
}

// ---------------- final mapping + output pack ----------------
__global__ void out_k(const int* __restrict__ pi, const float* __restrict__ ll,
                      void* __restrict__ out, int out_size)
{
    int b = blockIdx.x * blockDim.x + threadIdx.x;
    if (b >= Bsz) return;
    const int nodes[Psz] = {0,0,0,0, 1,1,1,1, 2,2,2,2, 3,3,3,3};
    int mp[Psz];
#pragma unroll
    for (int k = 0; k < Psz; k++) mp[k] = -1;
#pragma unroll
    for (int q = 0; q < Psz; q++) mp[pi[b * Psz + q]] = nodes[q];

    if (out_size >= Bsz * Psz + Bsz) {
        float* o = (float*)out;
#pragma unroll
        for (int k = 0; k < Psz; k++) o[b * Psz + k] = (float)mp[k];
        o[Bsz * Psz + b] = ll[b];
    } else {
        int* o = (int*)out;
#pragma unroll
        for (int k = 0; k < Psz; k++) o[b * Psz + k] = mp[k];
    }
}

// ---------------- host side ----------------
extern "C" void kernel_launch(void* const* d_in, const int* in_sizes, int n_in,
                              void* d_out, int out_size)
{
    const float* x        = (const float*)d_in[0];
    const float* emb_W    = (const float*)d_in[1];
    const float* enc_Wih  = (const float*)d_in[2];
    const float* enc_Whh  = (const float*)d_in[3];
    const float* enc_b    = (const float*)d_in[4];
    const float* dec_Wih  = (const float*)d_in[5];
    const float* dec_Whh  = (const float*)d_in[6];
    const float* dec_b    = (const float*)d_in[7];
    const float* Wq2      = (const float*)d_in[8];
    const float* bq2      = (const float*)d_in[9];
    const float* Wref2    = (const float*)d_in[10];
    const float* bref2    = (const float*)d_in[11];
    const float* Vec2     = (const float*)d_in[12];
    const float* dec0     = (const float*)d_in[13];

    float *u2, *inpenc, *inpdec, *dec0g, *c, *qp, *mask, *ll;
    float *Wenc, *benc, *Wdec, *bdec;
    int *pi, *sel;
    __half *X0,*X1, *E0,*E1, *R0,*R1, *Ha0,*Ha1, *Hb0,*Hb1;
    __half *EW0,*EW1, *WE0,*WE1, *WD0,*WD1, *WEH0,*WEH1, *WDH0,*WDH1, *WQ0,*WQ1, *WR0,*WR1;

    cudaGetSymbolAddress((void**)&u2,     g_u2);
    cudaGetSymbolAddress((void**)&inpenc, g_inpenc);
    cudaGetSymbolAddress((void**)&inpdec, g_inpdec);
    cudaGetSymbolAddress((void**)&dec0g,  g_dec0g);
    cudaGetSymbolAddress((void**)&c,      g_c);
    cudaGetSymbolAddress((void**)&qp,     g_qp);
    cudaGetSymbolAddress((void**)&mask,   g_mask);
    cudaGetSymbolAddress((void**)&ll,     g_ll);
    cudaGetSymbolAddress((void**)&pi,     g_pi);
    cudaGetSymbolAddress((void**)&sel,    g_sel);
    cudaGetSymbolAddress((void**)&Wenc,   g_Wenc);
    cudaGetSymbolAddress((void**)&benc,   g_benc);
    cudaGetSymbolAddress((void**)&Wdec,   g_Wdec);
    cudaGetSymbolAddress((void**)&bdec,   g_bdec);
    cudaGetSymbolAddress((void**)&X0, g_X0);   cudaGetSymbolAddress((void**)&X1, g_X1);
    cudaGetSymbolAddress((void**)&E0, g_E0);   cudaGetSymbolAddress((void**)&E1, g_E1);
    cudaGetSymbolAddress((void**)&R0, g_R0);   cudaGetSymbolAddress((void**)&R1, g_R1);
    cudaGetSymbolAddress((void**)&Ha0, g_Ha0); cudaGetSymbolAddress((void**)&Ha1, g_Ha1);
    cudaGetSymbolAddress((void**)&Hb0, g_Hb0); cudaGetSymbolAddress((void**)&Hb1, g_Hb1);
    cudaGetSymbolAddress((void**)&EW0, g_EW0); cudaGetSymbolAddress((void**)&EW1, g_EW1);
    cudaGetSymbolAddress((void**)&WE0, g_WE0); cudaGetSymbolAddress((void**)&WE1, g_WE1);
    cudaGetSymbolAddress((void**)&WD0, g_WD0); cudaGetSymbolAddress((void**)&WD1, g_WD1);
    cudaGetSymbolAddress((void**)&WEH0, g_WEH0); cudaGetSymbolAddress((void**)&WEH1, g_WEH1);
    cudaGetSymbolAddress((void**)&WDH0, g_WDH0); cudaGetSymbolAddress((void**)&WDH1, g_WDH1);
    cudaGetSymbolAddress((void**)&WQ0, g_WQ0); cudaGetSymbolAddress((void**)&WQ1, g_WQ1);
    cudaGetSymbolAddress((void**)&WR0, g_WR0); cudaGetSymbolAddress((void**)&WR1, g_WR1);

    cudaFuncSetAttribute(hmma_k<0>, cudaFuncAttributeMaxDynamicSharedMemorySize, HSM);
    cudaFuncSetAttribute(hmma_k<1>, cudaFuncAttributeMaxDynamicSharedMemorySize, HSM);
    cudaFuncSetAttribute(hmma_k<2>, cudaFuncAttributeMaxDynamicSharedMemorySize, HSM);

    const int RT = NG * KCAT;
    reorder_k<<<(RT + 255) / 256, 256>>>(enc_Wih, enc_Whh, enc_b, Wenc, benc);
    reorder_k<<<(RT + 255) / 256, 256>>>(dec_Wih, dec_Whh, dec_b, Wdec, bdec);
    init_k<<<(Bsz * Hsz + 255) / 256, 256>>>();
    dec0_k<<<NG / 8, 256>>>(dec0, Wdec, dec0g);

    // operand splits (all scaled by 64)
    split2_k<<<(MROWS * Gsz + 255) / 256, 256>>>(x, Gsz, Gsz, X0, X1, MROWS * Gsz);
    split2_k<<<(Esz * Gsz + 255) / 256, 256>>>(emb_W, Gsz, Gsz, EW0, EW1, Esz * Gsz);
    split2_k<<<(NG * Esz + 255) / 256, 256>>>(Wenc, KCAT, Esz, WE0, WE1, NG * Esz);
    split2_k<<<(NG * Esz + 255) / 256, 256>>>(Wdec, KCAT, Esz, WD0, WD1, NG * Esz);
    split2_k<<<(NG * Hsz + 255) / 256, 256>>>(Wenc + Esz, KCAT, Hsz, WEH0, WEH1, NG * Hsz);
    split2_k<<<(NG * Hsz + 255) / 256, 256>>>(Wdec + Esz, KCAT, Hsz, WDH0, WDH1, NG * Hsz);
    split2_k<<<(Hsz * Hsz + 255) / 256, 256>>>(Wq2, Hsz, Hsz, WQ0, WQ1, Hsz * Hsz);
    split2_k<<<(Hsz * Hsz + 255) / 256, 256>>>(Wref2, Hsz, Hsz, WR0, WR1, Hsz * Hsz);

    // emb = x @ emb_W^T -> fp16 splits E
    hmma_k<1><<<dim3(Esz / 128, MROWS / 128), 256, HSM>>>(
        X0, X1, EW0, EW1, Gsz, nullptr, nullptr, Esz,
        E0, E1, nullptr, 0, nullptr, 0, nullptr,
        nullptr, nullptr, nullptr, nullptr);

    // inp_enc / inp_dec tables (fp32)
    hmma_k<0><<<dim3(NG / 128, MROWS / 128), 256, HSM>>>(
        E0, E1, WE0, WE1, Esz, nullptr, inpenc, NG,
        nullptr, nullptr, nullptr, 0, nullptr, 0, nullptr,
        nullptr, nullptr, nullptr, nullptr);
    hmma_k<0><<<dim3(NG / 128, MROWS / 128), 256, HSM>>>(
        E0, E1, WD0, WD1, Esz, nullptr, inpdec, NG,
        nullptr, nullptr, nullptr, 0, nullptr, 0, nullptr,
        nullptr, nullptr, nullptr, nullptr);

    // ---- encoder: 16 fused LSTM steps ----
    __half *hc0 = Ha0, *hc1 = Ha1;
    __half *hn0 = Hb0, *hn1 = Hb1;
    for (int t = 0; t < Ssz; t++) {
        hmma_k<2><<<dim3(NG / 128, Bsz / 128), 256, HSM>>>(
            hc0, hc1, WEH0, WEH1, Hsz, benc, nullptr, NG,
            nullptr, nullptr,
            inpenc, (long long)Ssz * NG, nullptr, t,
            c, hn0, hn1, R0, R1);
        __half* t0 = hc0; hc0 = hn0; hn0 = t0;
        __half* t1 = hc1; hc1 = hn1; hn1 = t1;
    }

    // u2 = ref @ Wref2^T + bref2
    hmma_k<0><<<dim3(Hsz / 128, MROWS / 128), 256, HSM>>>(
        R0, R1, WR0, WR1, Hsz, bref2, u2, Hsz,
        nullptr, nullptr, nullptr, 0, nullptr, 0, nullptr,
        nullptr, nullptr, nullptr, nullptr);

    // ---- decoder: 16 fused steps + pointer ----
    for (int p = 0; p < Psz; p++) {
        if (p == 0) {
            hmma_k<2><<<dim3(NG / 128, Bsz / 128), 256, HSM>>>(
                hc0, hc1, WDH0, WDH1, Hsz, bdec, nullptr, NG,
                nullptr, nullptr,
                dec0g, 0LL, nullptr, 0,
                c, hn0, hn1, nullptr, nullptr);
        } else {
            hmma_k<2><<<dim3(NG / 128, Bsz / 128), 256, HSM>>>(
                hc0, hc1, WDH0, WDH1, Hsz, bdec, nullptr, NG,
                nullptr, nullptr,
                inpdec, (long long)Ssz * NG, sel, 0,
                c, hn0, hn1, nullptr, nullptr);
        }
        __half* t0 = hc0; hc0 = hn0; hn0 = t0;
        __half* t1 = hc1; hc1 = hn1; hn1 = t1;

        // qp = h @ Wq2^T + bq2
        hmma_k<0><<<dim3(Hsz / 128, Bsz / 128), 256, HSM>>>(
            hc0, hc1, WQ0, WQ1, Hsz, bq2, qp, Hsz,
            nullptr, nullptr, nullptr, 0, nullptr, 0, nullptr,
            nullptr, nullptr, nullptr, nullptr);

        pointer_k<<<Bsz, 256>>>(qp, u2, Vec2, mask, ll, pi, sel, p);
    }

    out_k<<<(Bsz + 255) / 256, 256>>>(pi, ll, d_out, out_size);
}

// round 7
// speedup vs baseline: 2.1391x; 1.0265x over previous
#include <cuda_runtime.h>
#include <cuda_fp16.h>
#include <math.h>
#include <stdint.h>

#define Bsz 4096
#define Ssz 16
#define Gsz 128
#define Esz 256
#define Hsz 512
#define Psz 16
#define KCAT (Esz + Hsz)   /* 768 */
#define NG   (4 * Hsz)     /* 2048 */
#define MROWS (Bsz * Ssz)  /* 65536 */

#define SCALE_UP 64.0f
#define SC (1.0f / 4096.0f)   /* 2^-12 epilogue unscale */

// ---------------- scratch (device globals; no allocation allowed) ----------------
__device__ float g_u2 [MROWS * Hsz];
__device__ float g_inpenc[MROWS * NG];
__device__ float g_inpdec[MROWS * NG];
__device__ float g_dec0g[NG];
__device__ float g_c  [Bsz * Hsz];
__device__ float g_qp [Bsz * Hsz];
__device__ float g_mask[Bsz * Ssz];
__device__ float g_ll [Bsz];
__device__ int   g_pi [Bsz * Psz];
__device__ int   g_sel[Bsz];
__device__ float g_Wenc[NG * KCAT];
__device__ float g_benc[NG];
__device__ float g_Wdec[NG * KCAT];
__device__ float g_bdec[NG];

// fp16 2-way split operands (all pre-scaled by 64)
__device__ __align__(128) __half g_X0[MROWS * Gsz],  g_X1[MROWS * Gsz];
__device__ __align__(128) __half g_E0[MROWS * Esz],  g_E1[MROWS * Esz];
__device__ __align__(128) __half g_R0[MROWS * Hsz],  g_R1[MROWS * Hsz];
__device__ __align__(128) __half g_Ha0[Bsz * Hsz], g_Ha1[Bsz * Hsz];
__device__ __align__(128) __half g_Hb0[Bsz * Hsz], g_Hb1[Bsz * Hsz];
__device__ __align__(128) __half g_EW0[Esz * Gsz],  g_EW1[Esz * Gsz];
__device__ __align__(128) __half g_WE0[NG * Esz],   g_WE1[NG * Esz];
__device__ __align__(128) __half g_WD0[NG * Esz],   g_WD1[NG * Esz];
__device__ __align__(128) __half g_WEH0[NG * Hsz],  g_WEH1[NG * Hsz];
__device__ __align__(128) __half g_WDH0[NG * Hsz],  g_WDH1[NG * Hsz];
__device__ __align__(128) __half g_WQ0[Hsz * Hsz],  g_WQ1[Hsz * Hsz];
__device__ __align__(128) __half g_WR0[Hsz * Hsz],  g_WR1[Hsz * Hsz];

static __device__ __forceinline__ float sigf(float x) { return 1.0f / (1.0f + expf(-x)); }

// ---------------- low-level helpers ----------------
static __device__ __forceinline__ uint32_t smem_u32(const void* p) {
    uint32_t a;
    asm("{ .reg .u64 t; cvta.to.shared.u64 t, %1; cvt.u32.u64 %0, t; }" : "=r"(a) : "l"(p));
    return a;
}
static __device__ __forceinline__ void ldsm4(uint32_t* r, uint32_t addr) {
    asm volatile("ldmatrix.sync.aligned.m8n8.x4.shared.b16 {%0,%1,%2,%3}, [%4];"
        : "=r"(r[0]), "=r"(r[1]), "=r"(r[2]), "=r"(r[3]) : "r"(addr));
}
static __device__ __forceinline__ void mma16816(float* d, const uint32_t* a, uint32_t b0, uint32_t b1) {
    asm volatile("mma.sync.aligned.m16n8k16.row.col.f32.f16.f16.f32 "
        "{%0,%1,%2,%3}, {%4,%5,%6,%7}, {%8,%9}, {%0,%1,%2,%3};"
        : "+f"(d[0]), "+f"(d[1]), "+f"(d[2]), "+f"(d[3])
        : "r"(a[0]), "r"(a[1]), "r"(a[2]), "r"(a[3]), "r"(b0), "r"(b1));
}
#define CPA(s, g) asm volatile("cp.async.cg.shared.global [%0], [%1], 16;" :: "r"(s), "l"(g))
#define CPC()     asm volatile("cp.async.commit_group;" ::: "memory")
template <int Ngrp> static __device__ __forceinline__ void cpwait() {
    asm volatile("cp.async.wait_group %0;" :: "n"(Ngrp) : "memory");
}

// scaled fp16 2-split: v -> (h0, h1) with h0 + h1 == 64*v (to fp16x2 precision)
static __device__ __forceinline__ void split1h(float v, __half& h0, __half& h1) {
    float vs = v * SCALE_UP;
    h0 = __float2half_rn(vs);
    h1 = __float2half_rn(vs - __half2float(h0));
}

// ---------------- scaled fp16 split of an fp32 matrix ----------------
__global__ void split2_k(const float* __restrict__ src, int lds, int K,
                         __half* __restrict__ d0, __half* __restrict__ d1, int total)
{
    int idx = blockIdx.x * blockDim.x + threadIdx.x;
    if (idx >= total) return;
    int r = idx / K, k = idx - r * K;
    float v = src[(size_t)r * lds + k];
    __half h0, h1;
    split1h(v, h0, h1);
    d0[idx] = h0; d1[idx] = h1;
}

// ---------------- weight reorder: new row 4*j+g <- old row g*H+j, cols = [Wih|Whh] ----
__global__ void reorder_k(const float* __restrict__ Wih, const float* __restrict__ Whh,
                          const float* __restrict__ b,
                          float* __restrict__ Wcat, float* __restrict__ bcat)
{
    int idx = blockIdx.x * blockDim.x + threadIdx.x;
    if (idx >= NG * KCAT) return;
    int r = idx / KCAT, k = idx % KCAT;
    int j = r >> 2, g = r & 3;
    int ro = g * Hsz + j;
    Wcat[idx] = (k < Esz) ? Wih[ro * Esz + k] : Whh[ro * Hsz + (k - Esz)];
    if (k == 0) bcat[r] = b[ro];
}

// ---------------- dec_input0 gate projection ----------------
__global__ void dec0_k(const float* __restrict__ dec0, const float* __restrict__ Wdec,
                       float* __restrict__ out)
{
    int n = blockIdx.x * 8 + (threadIdx.x >> 5);
    int lane = threadIdx.x & 31;
    const float* wr = Wdec + (size_t)n * KCAT;
    float s = 0.f;
#pragma unroll
    for (int k = lane; k < Esz; k += 32) s += dec0[k] * wr[k];
#pragma unroll
    for (int o = 16; o; o >>= 1) s += __shfl_xor_sync(0xffffffffu, s, o);
    if (lane == 0) out[n] = s;
}

// ---------------- init state ----------------
__global__ void init_k()
{
    int i = blockIdx.x * blockDim.x + threadIdx.x;
    if (i < Bsz * Hsz) {
        g_c[i] = 0.f;
        g_Ha0[i] = __float2half(0.f);
        g_Ha1[i] = __float2half(0.f);
    }
    if (i < Bsz * Ssz) g_mask[i] = 0.f;
    if (i < Bsz)       g_ll[i] = 0.f;
}

// ================= HMMA fp16 2-split GEMM =================
// C[m,n] = SC * sum_k As[m,k]*Ws[n,k], 3 terms: a0b0 + a1b0 + a0b1
// Tile 128x128xK, BK=32, 8 warps (4m x 2n), warp tile 32x64, cp.async double buffer.
// Single __syncthreads per chunk: wait<0>; sync; issue loads(cc+1); compute(cc).
// MODE 0: fp32 out (+bias). MODE 1: fp16-split out. MODE 2: fused LSTM epilogue.
#define RS 80                 /* smem row stride bytes — conflict-free ldmatrix */
#define OPB (128 * RS)        /* 10240 bytes per operand tile */
#define STGB (4 * OPB)        /* 40960 per stage */
#define HSM (2 * STGB)        /* 81920 total dynamic smem */

template <int MODE>
__global__ void __launch_bounds__(256, 2) hmma_k(
    const __half* __restrict__ A0, const __half* __restrict__ A1,
    const __half* __restrict__ B0, const __half* __restrict__ B1,
    int K, const float* __restrict__ bias,
    float* __restrict__ C, int N,
    __half* __restrict__ S0, __half* __restrict__ S1,
    const float* __restrict__ inp, long long mstride, const int* __restrict__ sel, int trow,
    float* __restrict__ cstate,
    __half* __restrict__ H0, __half* __restrict__ H1,
    __half* __restrict__ R0, __half* __restrict__ R1)
{
    extern __shared__ __align__(128) char smem[];
    const uint32_t sb = smem_u32(smem);
    const int tid = threadIdx.x, wid = tid >> 5, lane = tid & 31;
    const int wm = wid & 3, wn = wid >> 2;
    const int bn = blockIdx.x * 128, bm = blockIdx.y * 128;

    float D[2][8][4];
#pragma unroll
    for (int i = 0; i < 2; i++)
#pragma unroll
        for (int j = 0; j < 8; j++)
#pragma unroll
            for (int q = 0; q < 4; q++) D[i][j][q] = 0.f;

    const int grow = tid >> 1;
    const int gco  = (tid & 1) * 16;
    const __half* gA[2] = {A0 + (size_t)(bm + grow) * K, A1 + (size_t)(bm + grow) * K};
    const __half* gB[2] = {B0 + (size_t)(bn + grow) * K, B1 + (size_t)(bn + grow) * K};
    const uint32_t srow = sb + grow * RS + (tid & 1) * 32;

    auto stage_load = [&](int cc, int buf) {
        const int kc = cc * 32 + gco;
        const uint32_t s0 = srow + buf * STGB;
#pragma unroll
        for (int s = 0; s < 2; s++) {
            CPA(s0 + s * OPB, gA[s] + kc);
            CPA(s0 + s * OPB + 16, gA[s] + kc + 8);
            CPA(s0 + (2 + s) * OPB, gB[s] + kc);
            CPA(s0 + (2 + s) * OPB + 16, gB[s] + kc + 8);
        }
    };

    const int la = lane & 7, lb3 = (lane >> 3) & 1, lb4 = (lane >> 4) & 1;
    const uint32_t aAddr = sb + (uint32_t)(wm * 32 + la + lb3 * 8) * RS + (uint32_t)(lb4 * 8) * 2;
    const uint32_t bAddr = sb + 2 * OPB + (uint32_t)(wn * 64 + la + lb4 * 8) * RS + (uint32_t)(lb3 * 8) * 2;

    const int chunks = K >> 5;
    stage_load(0, 0); CPC();

    for (int cc = 0; cc < chunks; cc++) {
        const int buf = cc & 1;
        cpwait<0>();           // stage cc landed (only group in flight)
        __syncthreads();       // all warps done reading buf^1 (chunk cc-1)
        if (cc + 1 < chunks) { stage_load(cc + 1, buf ^ 1); CPC(); }

        const uint32_t aB = aAddr + buf * STGB;
        const uint32_t bB = bAddr + buf * STGB;
#pragma unroll
        for (int ks = 0; ks < 2; ks++) {
            uint32_t a[2][2][4];
#pragma unroll
            for (int s = 0; s < 2; s++) {
                ldsm4(a[s][0], aB + s * OPB + ks * 32);
                ldsm4(a[s][1], aB + s * OPB + ks * 32 + 16 * RS);
            }
            // bs = 0: as in {0,1}; bs = 1: as in {0}
#pragma unroll
            for (int bs = 0; bs < 2; bs++) {
                uint32_t b[4][4];
#pragma unroll
                for (int n16 = 0; n16 < 4; n16++)
                    ldsm4(b[n16], bB + bs * OPB + ks * 32 + n16 * 16 * RS);
                const int nas = (bs == 0) ? 2 : 1;
#pragma unroll
                for (int as = 0; as < 2; as++) {
                    if (as >= nas) break;
#pragma unroll
                    for (int mi = 0; mi < 2; mi++)
#pragma unroll
                        for (int n16 = 0; n16 < 4; n16++) {
                            mma16816(D[mi][2 * n16],     a[as][mi], b[n16][0], b[n16][1]);
                            mma16816(D[mi][2 * n16 + 1], a[as][mi], b[n16][2], b[n16][3]);
                        }
                }
            }
        }
    }

    // ---------------- epilogues ----------------
    const int c4 = lane & 3, r4 = lane >> 2;
    if (MODE == 0 || MODE == 1) {
#pragma unroll
        for (int mi = 0; mi < 2; mi++) {
            const int m0 = bm + wm * 32 + mi * 16 + r4;
#pragma unroll
            for (int nt = 0; nt < 8; nt++) {
                const int n0 = bn + wn * 64 + nt * 8 + c4 * 2;
                float bx = 0.f, by = 0.f;
                if (MODE == 0 && bias) { float2 bb = *(const float2*)(bias + n0); bx = bb.x; by = bb.y; }
                float v0 = D[mi][nt][0] * SC + bx, v1 = D[mi][nt][1] * SC + by;
                float v2 = D[mi][nt][2] * SC + bx, v3 = D[mi][nt][3] * SC + by;
                size_t o0 = (size_t)m0 * N + n0;
                size_t o1 = o0 + (size_t)8 * N;
                if (MODE == 0) {
                    *(float2*)(C + o0) = make_float2(v0, v1);
                    *(float2*)(C + o1) = make_float2(v2, v3);
                } else {
                    __half x0, x1, y0, y1;
                    __half2 p;
                    split1h(v0, x0, x1); split1h(v1, y0, y1);
                    p.x = x0; p.y = y0; *(__half2*)(S0 + o0) = p;
                    p.x = x1; p.y = y1; *(__half2*)(S1 + o0) = p;
                    split1h(v2, x0, x1); split1h(v3, y0, y1);
                    p.x = x0; p.y = y0; *(__half2*)(S0 + o1) = p;
                    p.x = x1; p.y = y1; *(__half2*)(S1 + o1) = p;
                }
            }
        }
    } else {
        // LSTM: cols gate-interleaved (i,f,g,o per unit). Lane pair exchange via shfl.
#pragma unroll
        for (int mi = 0; mi < 2; mi++) {
            const int mA = bm + wm * 32 + mi * 16 + r4;
            const int mB = mA + 8;
            const long long offA = (long long)mA * mstride + (long long)(sel ? sel[mA] : trow) * NG;
            const long long offB = (long long)mB * mstride + (long long)(sel ? sel[mB] : trow) * NG;
#pragma unroll
            for (int nt = 0; nt < 8; nt++) {
                float d0 = D[mi][nt][0] * SC, d1 = D[mi][nt][1] * SC;
                float d2 = D[mi][nt][2] * SC, d3 = D[mi][nt][3] * SC;
                float e0 = __shfl_xor_sync(0xffffffffu, d0, 1);
                float e1 = __shfl_xor_sync(0xffffffffu, d1, 1);
                float e2 = __shfl_xor_sync(0xffffffffu, d2, 1);
                float e3 = __shfl_xor_sync(0xffffffffu, d3, 1);
                if (!(c4 & 1)) {
                    const int ucol = bn + wn * 64 + nt * 8 + c4 * 2;
                    const int unit = ucol >> 2;
                    const float4 bb = *(const float4*)(bias + ucol);
                    const float4 gA = *(const float4*)(inp + offA + ucol);
                    const float4 gB = *(const float4*)(inp + offB + ucol);
                    {
                        float gi = sigf(d0 + gA.x + bb.x);
                        float gf = sigf(d1 + gA.y + bb.y);
                        float gg = tanhf(e0 + gA.z + bb.z);
                        float go = sigf(e1 + gA.w + bb.w);
                        size_t ci = (size_t)mA * Hsz + unit;
                        float cn = gf * cstate[ci] + gi * gg;
                        float hn = go * tanhf(cn);
                        cstate[ci] = cn;
                        __half h0, h1; split1h(hn, h0, h1);
                        H0[ci] = h0; H1[ci] = h1;
                        if (R0) {
                            size_t ri = ((size_t)mA * Ssz + trow) * Hsz + unit;
                            R0[ri] = h0; R1[ri] = h1;
                        }
                    }
                    {
                        float gi = sigf(d2 + gB.x + bb.x);
                        float gf = sigf(d3 + gB.y + bb.y);
                        float gg = tanhf(e2 + gB.z + bb.z);
                        float go = sigf(e3 + gB.w + bb.w);
                        size_t ci = (size_t)mB * Hsz + unit;
                        float cn = gf * cstate[ci] + gi * gg;
                        float hn = go * tanhf(cn);
                        cstate[ci] = cn;
                        __half h0, h1; split1h(hn, h0, h1);
                        H0[ci] = h0; H1[ci] = h1;
                        if (R0) {
                            size_t ri = ((size_t)mB * Ssz + trow) * Hsz + unit;
                            R0[ri] = h0; R1[ri] = h1;
                        }
                    }
                }
            }
        }
    }
}

// ---------------- pointer step ----------------
__global__ void pointer_k(const float* __restrict__ qp, const float* __restrict__ u2,
                          const float* __restrict__ Vec2,
                          float* __restrict__ mask, float* __restrict__ ll,
                          int* __restrict__ pi, int* __restrict__ sel, int p)
{
    const int b = blockIdx.x;
    const int tid = threadIdx.x;
    const int lane = tid & 31, w = tid >> 5;
    __shared__ float qs[Hsz], vs[Hsz], ls[Ssz];

    qs[tid]       = qp[(size_t)b * Hsz + tid];
    qs[tid + 256] = qp[(size_t)b * Hsz + 256 + tid];
    vs[tid]       = Vec2[tid];
    vs[tid + 256] = Vec2[tid + 256];
    __syncthreads();

#pragma unroll
    for (int q = 0; q < 2; q++) {
        int ss = 2 * w + q;
        const float* up = u2 + ((size_t)b * Ssz + ss) * Hsz;
        float acc = 0.f;
#pragma unroll
        for (int it = 0; it < Hsz / 32; it++) {
            int h = lane + 32 * it;
            acc += vs[h] * tanhf(qs[h] + up[h]);
        }
#pragma unroll
        for (int o = 16; o; o >>= 1) acc += __shfl_xor_sync(0xffffffffu, acc, o);
        if (lane == 0) ls[ss] = 10.0f * acc - 1e8f * mask[b * Ssz + ss];
    }
    __syncthreads();

    if (w == 0) {
        float v  = (lane < Ssz) ? ls[lane] : -INFINITY;
        int   id = (lane < Ssz) ? lane : Ssz;
        float bv = v; int bi = id;
#pragma unroll
        for (int o = 8; o; o >>= 1) {
            float ov = __shfl_xor_sync(0xffffffffu, bv, o);
            int   oi = __shfl_xor_sync(0xffffffffu, bi, o);
            if (ov > bv || (ov == bv && oi < bi)) { bv = ov; bi = oi; }
        }
        float ex = (lane < Ssz) ? expf(v - bv) : 0.f;
#pragma unroll
        for (int o = 16; o; o >>= 1) ex += __shfl_xor_sync(0xffffffffu, ex, o);
        if (lane == 0) {
            float lse = bv + logf(ex);
            ll[b] += bv - lse;
            pi[b * Psz + p] = bi;
            sel[b] = bi;
            mask[b * Ssz + bi] += 1.0f;
        }
    }
}

// ---------------- final mapping + output pack ----------------
__global__ void out_k(const int* __restrict__ pi, const float* __restrict__ ll,
                      void* __restrict__ out, int out_size)
{
    int b = blockIdx.x * blockDim.x + threadIdx.x;
    if (b >= Bsz) return;
    const int nodes[Psz] = {0,0,0,0, 1,1,1,1, 2,2,2,2, 3,3,3,3};
    int mp[Psz];
#pragma unroll
    for (int k = 0; k < Psz; k++) mp[k] = -1;
#pragma unroll
    for (int q = 0; q < Psz; q++) mp[pi[b * Psz + q]] = nodes[q];

    if (out_size >= Bsz * Psz + Bsz) {
        float* o = (float*)out;
#pragma unroll
        for (int k = 0; k < Psz; k++) o[b * Psz + k] = (float)mp[k];
        o[Bsz * Psz + b] = ll[b];
    } else {
        int* o = (int*)out;
#pragma unroll
        for (int k = 0; k < Psz; k++) o[b * Psz + k] = mp[k];
    }
}

// ---------------- host side ----------------
extern "C" void kernel_launch(void* const* d_in, const int* in_sizes, int n_in,
                              void* d_out, int out_size)
{
    const float* x        = (const float*)d_in[0];
    const float* emb_W    = (const float*)d_in[1];
    const float* enc_Wih  = (const float*)d_in[2];
    const float* enc_Whh  = (const float*)d_in[3];
    const float* enc_b    = (const float*)d_in[4];
    const float* dec_Wih  = (const float*)d_in[5];
    const float* dec_Whh  = (const float*)d_in[6];
    const float* dec_b    = (const float*)d_in[7];
    const float* Wq2      = (const float*)d_in[8];
    const float* bq2      = (const float*)d_in[9];
    const float* Wref2    = (const float*)d_in[10];
    const float* bref2    = (const float*)d_in[11];
    const float* Vec2     = (const float*)d_in[12];
    const float* dec0     = (const float*)d_in[13];

    float *u2, *inpenc, *inpdec, *dec0g, *c, *qp, *mask, *ll;
    float *Wenc, *benc, *Wdec, *bdec;
    int *pi, *sel;
    __half *X0,*X1, *E0,*E1, *R0,*R1, *Ha0,*Ha1, *Hb0,*Hb1;
    __half *EW0,*EW1, *WE0,*WE1, *WD0,*WD1, *WEH0,*WEH1, *WDH0,*WDH1, *WQ0,*WQ1, *WR0,*WR1;

    cudaGetSymbolAddress((void**)&u2,     g_u2);
    cudaGetSymbolAddress((void**)&inpenc, g_inpenc);
    cudaGetSymbolAddress((void**)&inpdec, g_inpdec);
    cudaGetSymbolAddress((void**)&dec0g,  g_dec0g);
    cudaGetSymbolAddress((void**)&c,      g_c);
    cudaGetSymbolAddress((void**)&qp,     g_qp);
    cudaGetSymbolAddress((void**)&mask,   g_mask);
    cudaGetSymbolAddress((void**)&ll,     g_ll);
    cudaGetSymbolAddress((void**)&pi,     g_pi);
    cudaGetSymbolAddress((void**)&sel,    g_sel);
    cudaGetSymbolAddress((void**)&Wenc,   g_Wenc);
    cudaGetSymbolAddress((void**)&benc,   g_benc);
    cudaGetSymbolAddress((void**)&Wdec,   g_Wdec);
    cudaGetSymbolAddress((void**)&bdec,   g_bdec);
    cudaGetSymbolAddress((void**)&X0, g_X0);   cudaGetSymbolAddress((void**)&X1, g_X1);
    cudaGetSymbolAddress((void**)&E0, g_E0);   cudaGetSymbolAddress((void**)&E1, g_E1);
    cudaGetSymbolAddress((void**)&R0, g_R0);   cudaGetSymbolAddress((void**)&R1, g_R1);
    cudaGetSymbolAddress((void**)&Ha0, g_Ha0); cudaGetSymbolAddress((void**)&Ha1, g_Ha1);
    cudaGetSymbolAddress((void**)&Hb0, g_Hb0); cudaGetSymbolAddress((void**)&Hb1, g_Hb1);
    cudaGetSymbolAddress((void**)&EW0, g_EW0); cudaGetSymbolAddress((void**)&EW1, g_EW1);
    cudaGetSymbolAddress((void**)&WE0, g_WE0); cudaGetSymbolAddress((void**)&WE1, g_WE1);
    cudaGetSymbolAddress((void**)&WD0, g_WD0); cudaGetSymbolAddress((void**)&WD1, g_WD1);
    cudaGetSymbolAddress((void**)&WEH0, g_WEH0); cudaGetSymbolAddress((void**)&WEH1, g_WEH1);
    cudaGetSymbolAddress((void**)&WDH0, g_WDH0); cudaGetSymbolAddress((void**)&WDH1, g_WDH1);
    cudaGetSymbolAddress((void**)&WQ0, g_WQ0); cudaGetSymbolAddress((void**)&WQ1, g_WQ1);
    cudaGetSymbolAddress((void**)&WR0, g_WR0); cudaGetSymbolAddress((void**)&WR1, g_WR1);

    cudaFuncSetAttribute(hmma_k<0>, cudaFuncAttributeMaxDynamicSharedMemorySize, HSM);
    cudaFuncSetAttribute(hmma_k<1>, cudaFuncAttributeMaxDynamicSharedMemorySize, HSM);
    cudaFuncSetAttribute(hmma_k<2>, cudaFuncAttributeMaxDynamicSharedMemorySize, HSM);

    // ---- launch order arranged so ncu (-s 5 -c 1) profiles hmma_k<1> (launch #6) ----
    split2_k<<<(MROWS * Gsz + 255) / 256, 256>>>(x, Gsz, Gsz, X0, X1, MROWS * Gsz);          // 1
    split2_k<<<(Esz * Gsz + 255) / 256, 256>>>(emb_W, Gsz, Gsz, EW0, EW1, Esz * Gsz);        // 2
    const int RT = NG * KCAT;
    reorder_k<<<(RT + 255) / 256, 256>>>(enc_Wih, enc_Whh, enc_b, Wenc, benc);               // 3
    reorder_k<<<(RT + 255) / 256, 256>>>(dec_Wih, dec_Whh, dec_b, Wdec, bdec);               // 4
    init_k<<<(Bsz * Hsz + 255) / 256, 256>>>();                                              // 5

    // emb = x @ emb_W^T -> fp16 splits E       (launch #6 — profiled)
    hmma_k<1><<<dim3(Esz / 128, MROWS / 128), 256, HSM>>>(
        X0, X1, EW0, EW1, Gsz, nullptr, nullptr, Esz,
        E0, E1, nullptr, 0, nullptr, 0, nullptr,
        nullptr, nullptr, nullptr, nullptr);

    dec0_k<<<NG / 8, 256>>>(dec0, Wdec, dec0g);
    split2_k<<<(NG * Esz + 255) / 256, 256>>>(Wenc, KCAT, Esz, WE0, WE1, NG * Esz);
    split2_k<<<(NG * Esz + 255) / 256, 256>>>(Wdec, KCAT, Esz, WD0, WD1, NG * Esz);
    split2_k<<<(NG * Hsz + 255) / 256, 256>>>(Wenc + Esz, KCAT, Hsz, WEH0, WEH1, NG * Hsz);
    split2_k<<<(NG * Hsz + 255) / 256, 256>>>(Wdec + Esz, KCAT, Hsz, WDH0, WDH1, NG * Hsz);
    split2_k<<<(Hsz * Hsz + 255) / 256, 256>>>(Wq2, Hsz, Hsz, WQ0, WQ1, Hsz * Hsz);
    split2_k<<<(Hsz * Hsz + 255) / 256, 256>>>(Wref2, Hsz, Hsz, WR0, WR1, Hsz * Hsz);

    // inp_enc / inp_dec tables (fp32)
    hmma_k<0><<<dim3(NG / 128, MROWS / 128), 256, HSM>>>(
        E0, E1, WE0, WE1, Esz, nullptr, inpenc, NG,
        nullptr, nullptr, nullptr, 0, nullptr, 0, nullptr,
        nullptr, nullptr, nullptr, nullptr);
    hmma_k<0><<<dim3(NG / 128, MROWS / 128), 256, HSM>>>(
        E0, E1, WD0, WD1, Esz, nullptr, inpdec, NG,
        nullptr, nullptr, nullptr, 0, nullptr, 0, nullptr,
        nullptr, nullptr, nullptr, nullptr);

    // ---- encoder: 16 fused LSTM steps ----
    __half *hc0 = Ha0, *hc1 = Ha1;
    __half *hn0 = Hb0, *hn1 = Hb1;
    for (int t = 0; t < Ssz; t++) {
        hmma_k<2><<<dim3(NG / 128, Bsz / 128), 256, HSM>>>(
            hc0, hc1, WEH0, WEH1, Hsz, benc, nullptr, NG,
            nullptr, nullptr,
            inpenc, (long long)Ssz * NG, nullptr, t,
            c, hn0, hn1, R0, R1);
        __half* t0 = hc0; hc0 = hn0; hn0 = t0;
        __half* t1 = hc1; hc1 = hn1; hn1 = t1;
    }

    // u2 = ref @ Wref2^T + bref2
    hmma_k<0><<<dim3(Hsz / 128, MROWS / 128), 256, HSM>>>(
        R0, R1, WR0, WR1, Hsz, bref2, u2, Hsz,
        nullptr, nullptr, nullptr, 0, nullptr, 0, nullptr,
        nullptr, nullptr, nullptr, nullptr);

    // ---- decoder: 16 fused steps + pointer ----
    for (int p = 0; p < Psz; p++) {
        if (p == 0) {
            hmma_k<2><<<dim3(NG / 128, Bsz / 128), 256, HSM>>>(
                hc0, hc1, WDH0, WDH1, Hsz, bdec, nullptr, NG,
                nullptr, nullptr,
                dec0g, 0LL, nullptr, 0,
                c, hn0, hn1, nullptr, nullptr);
        } else {
            hmma_k<2><<<dim3(NG / 128, Bsz / 128), 256, HSM>>>(
                hc0, hc1, WDH0, WDH1, Hsz, bdec, nullptr, NG,
                nullptr, nullptr,
                inpdec, (long long)Ssz * NG, sel, 0,
                c, hn0, hn1, nullptr, nullptr);
        }
        __half* t0 = hc0; hc0 = hn0; hn0 = t0;
        __half* t1 = hc1; hc1 = hn1; hn1 = t1;

        // qp = h @ Wq2^T + bq2
        hmma_k<0><<<dim3(Hsz / 128, Bsz / 128), 256, HSM>>>(
            hc0, hc1, WQ0, WQ1, Hsz, bq2, qp, Hsz,
            nullptr, nullptr, nullptr, 0, nullptr, 0, nullptr,
            nullptr, nullptr, nullptr, nullptr);

        pointer_k<<<Bsz, 256>>>(qp, u2, Vec2, mask, ll, pi, sel, p);
    }

    out_k<<<(Bsz + 255) / 256, 256>>>(pi, ll, d_out, out_size);
}